// round 12
// baseline (speedup 1.0000x reference)
#include <cuda_runtime.h>
#include <cuda_bf16.h>

#define EPS     1e-5f
#define THREADS 256
#define TILE_M  128
#define NPTS    (64 * 1024)
#define NBLK    (NPTS / TILE_M)   // 512 CTAs

// ---- pre-folded weights ----
// W1 @0 (8192B, KT=2) and W2 @8192 (16384B, KT=4): B-fragment layout,
//   16B unit(o,t,p) = [hi frag 8B | lo frag 8B], t XOR-swizzled.
// W3 @24576 (16384B): A-fragment layout, per (mt,t) 1KB block:
//   hi a[4] (16B) at lane*16, lo a[4] at +512.
__device__ __align__(16) char  wbuf[40960];
__device__ __align__(16) float bbuf[192];

typedef unsigned long long ull;

// ---- packed fp32x2 helpers ----
__device__ __forceinline__ ull fma2(ull a, ull b, ull c) {
    ull d; asm("fma.rn.f32x2 %0,%1,%2,%3;" : "=l"(d) : "l"(a), "l"(b), "l"(c)); return d;
}
__device__ __forceinline__ ull mul2(ull a, ull b) {
    ull d; asm("mul.rn.f32x2 %0,%1,%2;" : "=l"(d) : "l"(a), "l"(b)); return d;
}
__device__ __forceinline__ void unpk(ull v, float& lo, float& hi) {
    asm("mov.b64 {%0,%1}, %2;" : "=f"(lo), "=f"(hi) : "l"(v));
}
__device__ __forceinline__ ull pk2(float lo, float hi) {
    ull v; asm("mov.b64 %0, {%1,%2};" : "=l"(v) : "f"(lo), "f"(hi)); return v;
}
__device__ __forceinline__ ull pkc(float c) {
    unsigned u = __float_as_uint(c); return ((ull)u << 32) | (ull)u;
}
__device__ __forceinline__ float frcp(float x) {
    float r; asm("rcp.approx.f32 %0,%1;" : "=f"(r) : "f"(x)); return r;
}

// Exact-class GELU on a packed pair via A&S 7.1.28 (|erf err|<=3e-7, branch-free):
// gelu(x) = 0.5x + 0.5|x|(1 - d^-16), d = 1 + a1 z + ... + a6 z^6, z = |x|/sqrt2.
__device__ __forceinline__ ull gelu2(ull s) {
    const ull C_ISQ2 = pkc(0.70710678118654752f);
    ull z = mul2(s & 0x7FFFFFFF7FFFFFFFULL, C_ISQ2);
    ull d = fma2(z, pkc(0.0000430638f), pkc(0.0002765672f));
    d = fma2(z, d, pkc(0.0001520143f));
    d = fma2(z, d, pkc(0.0092705272f));
    d = fma2(z, d, pkc(0.0422820123f));
    d = fma2(z, d, pkc(0.0705230784f));
    d = fma2(z, d, pkc(1.0f));
    d = mul2(d, d); d = mul2(d, d); d = mul2(d, d); d = mul2(d, d);   // d^16
    float dl, dh; unpk(d, dl, dh);
    ull r = pk2(frcp(dl), frcp(dh));                                  // d^-16
    ull u = mul2(z, C_ISQ2);                                          // 0.5|x|
    ull w = fma2(r ^ 0x8000000080000000ULL, u, u);                    // u(1-r)
    return fma2(s, pkc(0.5f), w);
}

// packed f32 pair -> (bf16x2 hi, bf16x2 lo-residual)
__device__ __forceinline__ void splitpair(ull v, unsigned& hb, unsigned& lb) {
    float f0, f1; unpk(v, f0, f1);
    unsigned h;
    asm("cvt.rn.bf16x2.f32 %0, %1, %2;" : "=r"(h) : "f"(f1), "f"(f0));
    float a0 = __uint_as_float(h << 16);
    float a1 = __uint_as_float(h & 0xFFFF0000u);
    float r0 = f0 - a0, r1 = f1 - a1;
    unsigned l;
    asm("cvt.rn.bf16x2.f32 %0, %1, %2;" : "=r"(l) : "f"(r1), "f"(r0));
    hb = h; lb = l;
}

// D += A @ B; fp32 accum. NOT volatile: pure register op, lets ptxas interleave.
__device__ __forceinline__ void mma16816(float d[4], const unsigned a[4],
                                         unsigned b0, unsigned b1) {
    asm("mma.sync.aligned.m16n8k16.row.col.f32.bf16.bf16.f32 "
        "{%0,%1,%2,%3},{%4,%5,%6,%7},{%8,%9},{%0,%1,%2,%3};"
        : "+f"(d[0]), "+f"(d[1]), "+f"(d[2]), "+f"(d[3])
        : "r"(a[0]), "r"(a[1]), "r"(a[2]), "r"(a[3]), "r"(b0), "r"(b1));
}

// B-fragment layout offset (W1/W2): 16B unit(o,t,p) = hi|lo
template<int KT>
__device__ __forceinline__ int woff16(int o, int k) {
    int t = k >> 4, kk = k & 15, pp = (kk & 7) >> 1, half = kk >> 3;
    int ts = t ^ (o & (KT - 1));
    return ((o * KT + ts) * 4 + pp) * 16 + half * 4 + (k & 1) * 2;
}

// A-fragment layout offset for W3 (hi; lo at +512)
__device__ __forceinline__ int woff_a3(int o, int k) {
    int mt = o >> 4, gg = o & 15, g = gg & 7, hi8 = gg >> 3;
    int t = k >> 4, kk = k & 15, pp = (kk & 7) >> 1, e = kk & 1, c8 = kk >> 3;
    int r = c8 * 2 + hi8;
    return (mt * 4 + t) * 1024 + ((g << 2) | pp) * 16 + (r << 2) + (e << 1);
}

// ---- one-shot fold kernel ----
__global__ void fold_kernel(
    const float* __restrict__ W1, const float* __restrict__ g1, const float* __restrict__ b1,
    const float* __restrict__ m1, const float* __restrict__ v1,
    const float* __restrict__ W2, const float* __restrict__ g2, const float* __restrict__ b2,
    const float* __restrict__ m2, const float* __restrict__ v2,
    const float* __restrict__ W3, const float* __restrict__ g3, const float* __restrict__ b3,
    const float* __restrict__ m3, const float* __restrict__ v3)
{
    int i = blockIdx.x * blockDim.x + threadIdx.x;
    if (i < 2048) {                               // W1 [64x32], B-frag layout
        int o = i >> 5, k = i & 31;
        float w = W1[i] * (g1[o] * rsqrtf(v1[o] + EPS));
        __nv_bfloat16 hi = __float2bfloat16(w);
        int off = woff16<2>(o, k);
        *(__nv_bfloat16*)(wbuf + off)     = hi;
        *(__nv_bfloat16*)(wbuf + off + 8) = __float2bfloat16(w - __bfloat162float(hi));
    } else if (i < 2048 + 4096) {                 // W2 [64x64], B-frag layout
        int j = i - 2048, o = j >> 6, k = j & 63;
        float w = W2[j] * (g2[o] * rsqrtf(v2[o] + EPS));
        __nv_bfloat16 hi = __float2bfloat16(w);
        int off = 8192 + woff16<4>(o, k);
        *(__nv_bfloat16*)(wbuf + off)     = hi;
        *(__nv_bfloat16*)(wbuf + off + 8) = __float2bfloat16(w - __bfloat162float(hi));
    } else if (i < 2048 + 8192) {                 // W3 [64x64], A-frag layout
        int j = i - 6144, o = j >> 6, k = j & 63;
        float w = W3[j] * (g3[o] * rsqrtf(v3[o] + EPS));
        __nv_bfloat16 hi = __float2bfloat16(w);
        int off = 24576 + woff_a3(o, k);
        *(__nv_bfloat16*)(wbuf + off)       = hi;
        *(__nv_bfloat16*)(wbuf + off + 512) = __float2bfloat16(w - __bfloat162float(hi));
    }
    if (i < 64) {
        bbuf[i]       = b1[i] - m1[i] * (g1[i] * rsqrtf(v1[i] + EPS));
        bbuf[64 + i]  = b2[i] - m2[i] * (g2[i] * rsqrtf(v2[i] + EPS));
        bbuf[128 + i] = b3[i] - m3[i] * (g3[i] * rsqrtf(v3[i] + EPS));
    }
    asm volatile("griddepcontrol.launch_dependents;");
}

// Stages 1-2 (act as A): D[8][4] = bias + (Ah+Al)@(Wh+Wl)^T, dropping lo*lo.
template<int KT>
__device__ __forceinline__ void run_stage(const char* w, const float* bias,
                                          unsigned Ah[4][4], unsigned Al[4][4],
                                          float D[8][4], int g, int p) {
    #pragma unroll
    for (int j = 0; j < 8; ++j) {
        float b0, b1;
        unpk(*(const ull*)(bias + 8 * j + 2 * p), b0, b1);
        D[j][0] = b0; D[j][1] = b1; D[j][2] = b0; D[j][3] = b1;
        int o = 8 * j + g;
        #pragma unroll
        for (int t = 0; t < KT; ++t) {
            int ts = t ^ (o & (KT - 1));
            int unit = (o * KT + ts) * 4 + p;
            ulonglong2 wv = *(const ulonglong2*)(w + unit * 16);   // one LDS.128: hi|lo
            unsigned bh0 = (unsigned)wv.x, bh1 = (unsigned)(wv.x >> 32);
            unsigned bl0 = (unsigned)wv.y, bl1 = (unsigned)(wv.y >> 32);
            mma16816(D[j], Ah[t], bh0, bh1);   // hi*hi
            mma16816(D[j], Ah[t], bl0, bl1);   // hi*lo
            mma16816(D[j], Al[t], bh0, bh1);   // lo*hi
        }
    }
}

// gelu + re-split into next stage's A fragments (pure per-thread register work)
__device__ __forceinline__ void epilogue_mid(float D[8][4],
                                             unsigned Ah[4][4], unsigned Al[4][4]) {
    #pragma unroll
    for (int j = 0; j < 8; ++j) {
        int t = j >> 1;
        int rb = (j & 1) ? 2 : 0;
        ull v0 = gelu2(pk2(D[j][0], D[j][1]));
        ull v1 = gelu2(pk2(D[j][2], D[j][3]));
        splitpair(v0, Ah[t][rb],     Al[t][rb]);
        splitpair(v1, Ah[t][rb + 1], Al[t][rb + 1]);
    }
}

__global__ void __launch_bounds__(THREADS, 2) mlp_mma_kernel(
    const float* __restrict__ x, float* __restrict__ out)
{
    __shared__ __align__(16) float sbias[256];
    __shared__ __align__(16) char  sw[40960];
    const int tid = threadIdx.x;
    const int lane = tid & 31, wid = tid >> 5;   // warp = one 16-row m-tile
    const int g = lane >> 2, p = lane & 3;

    // ---- PDL phase 1: fold-independent prologue (x LDG + A-fragment build) ----
    const int pbase = blockIdx.x * TILE_M;
    unsigned Ah[4][4], Al[4][4];
    {
        const float* xr = x + (size_t)(pbase + wid * 16 + g) * 32;   // row g; row g+8 = +256
        #pragma unroll
        for (int t = 0; t < 2; ++t) {
            int c0 = p * 2 + t * 16;
            splitpair(*(const ull*)(xr + c0),           Ah[t][0], Al[t][0]);
            splitpair(*(const ull*)(xr + 256 + c0),     Ah[t][1], Al[t][1]);
            splitpair(*(const ull*)(xr + c0 + 8),       Ah[t][2], Al[t][2]);
            splitpair(*(const ull*)(xr + 256 + c0 + 8), Ah[t][3], Al[t][3]);
        }
    }

    // ---- PDL phase 2: wait for fold_kernel's weights, then stage them ----
    asm volatile("griddepcontrol.wait;" ::: "memory");
    {
        const uint4* src = (const uint4*)wbuf;
        uint4* dst = (uint4*)sw;
        #pragma unroll
        for (int i = 0; i < 10; ++i) dst[tid + i * THREADS] = src[tid + i * THREADS];
        if (tid < 48) ((uint4*)sbias)[tid] = ((const uint4*)bbuf)[tid];
    }
    __syncthreads();

    float D[8][4];

    run_stage<2>(sw,        sbias,      Ah, Al, D, g, p);
    epilogue_mid(D, Ah, Al);

    run_stage<4>(sw + 8192, sbias + 64, Ah, Al, D, g, p);
    epilogue_mid(D, Ah, Al);

    // ---- Stage 3: W3 as A, activations reused as B-fragments (layout identity) ----
    // b0,b1 for point-block nb == Ah[t][nb], Ah[t][nb+2] (verified vs PTX frag tables).
    float D3[4][2][4];
    #pragma unroll
    for (int mt = 0; mt < 4; ++mt) {
        float blo = sbias[128 + 16 * mt + g];
        float bhi = sbias[128 + 16 * mt + g + 8];
        #pragma unroll
        for (int nb = 0; nb < 2; ++nb) {
            D3[mt][nb][0] = blo; D3[mt][nb][1] = blo;
            D3[mt][nb][2] = bhi; D3[mt][nb][3] = bhi;
        }
        #pragma unroll
        for (int t = 0; t < 4; ++t) {
            const char* blk = sw + 24576 + (mt * 4 + t) * 1024 + lane * 16;
            uint4 whv = *(const uint4*)blk;            // hi a[4]
            uint4 wlv = *(const uint4*)(blk + 512);    // lo a[4]
            unsigned wh[4] = {whv.x, whv.y, whv.z, whv.w};
            unsigned wl[4] = {wlv.x, wlv.y, wlv.z, wlv.w};
            #pragma unroll
            for (int nb = 0; nb < 2; ++nb) {
                unsigned bh0 = Ah[t][nb], bh1 = Ah[t][nb + 2];
                unsigned bl0 = Al[t][nb], bl1 = Al[t][nb + 2];
                mma16816(D3[mt][nb], wh, bh0, bh1);   // hi*hi
                mma16816(D3[mt][nb], wh, bl0, bl1);   // hi*lo
                mma16816(D3[mt][nb], wl, bh0, bh1);   // lo*hi
            }
        }
    }

    // ---- final: gelu -> STG.64 (adjacent points, same output channel) ----
    float* outp = out + (size_t)(pbase >> 10) * 65536 + (pbase & 1023) + wid * 16;
    #pragma unroll
    for (int mt = 0; mt < 4; ++mt) {
        #pragma unroll
        for (int nb = 0; nb < 2; ++nb) {
            ull v0 = gelu2(pk2(D3[mt][nb][0], D3[mt][nb][1]));   // o = 16mt+g,   pts 2p,2p+1
            ull v1 = gelu2(pk2(D3[mt][nb][2], D3[mt][nb][3]));   // o = 16mt+g+8
            float* a = outp + (size_t)(16 * mt + g) * 1024 + 8 * nb + 2 * p;
            *(ull*)a = v0;
            *(ull*)(a + 8 * 1024) = v1;
        }
    }
}

extern "C" void kernel_launch(void* const* d_in, const int* in_sizes, int n_in,
                              void* d_out, int out_size)
{
    const float* x  = (const float*)d_in[0];
    const float* W1 = (const float*)d_in[1];
    const float* g1 = (const float*)d_in[2];
    const float* b1 = (const float*)d_in[3];
    const float* m1 = (const float*)d_in[4];
    const float* v1 = (const float*)d_in[5];
    const float* W2 = (const float*)d_in[6];
    const float* g2 = (const float*)d_in[7];
    const float* b2 = (const float*)d_in[8];
    const float* m2 = (const float*)d_in[9];
    const float* v2 = (const float*)d_in[10];
    const float* W3 = (const float*)d_in[11];
    const float* g3 = (const float*)d_in[12];
    const float* b3 = (const float*)d_in[13];
    const float* m3 = (const float*)d_in[14];
    const float* v3 = (const float*)d_in[15];
    float* out = (float*)d_out;

    fold_kernel<<<40, 256>>>(W1, g1, b1, m1, v1, W2, g2, b2, m2, v2, W3, g3, b3, m3, v3);

    cudaLaunchConfig_t cfg = {};
    cfg.gridDim = dim3(NBLK, 1, 1);
    cfg.blockDim = dim3(THREADS, 1, 1);
    cfg.dynamicSmemBytes = 0;
    cfg.stream = 0;
    cudaLaunchAttribute attrs[1];
    attrs[0].id = cudaLaunchAttributeProgrammaticStreamSerialization;
    attrs[0].val.programmaticStreamSerializationAllowed = 1;
    cfg.attrs = attrs;
    cfg.numAttrs = 1;
    cudaLaunchKernelEx(&cfg, mlp_mma_kernel, x, out);
}

// round 13
// speedup vs baseline: 1.0013x; 1.0013x over previous
#include <cuda_runtime.h>
#include <cuda_bf16.h>

#define EPS      1e-5f
#define THREADS  256
#define TILE_M   128
#define NPTS     (64 * 1024)
#define NTILES   (NPTS / TILE_M)     // 512
#define NBLK2    (NTILES / 2)        // 256 persistent CTAs, 2 tiles each

// ---- pre-folded weights ----
// W1 @0 (8192B, KT=2) and W2 @8192 (16384B, KT=4): B-fragment layout,
//   16B unit(o,t,p) = [hi frag 8B | lo frag 8B], t XOR-swizzled.
// W3 @24576 (16384B): A-fragment layout, per (mt,t) 1KB block:
//   hi a[4] (16B) at lane*16, lo a[4] at +512.
__device__ __align__(16) char  wbuf[40960];
__device__ __align__(16) float bbuf[192];

// ---- dynamic SMEM layout (bytes) ----
#define OFF_BIAS 0                   // 192 f32 (pad to 1024)
#define OFF_W    1024                // 40960
#define OFF_X    41984               // tile-2 x staging: 128 rows x 36 f32 = 18432
#define X_STRIDE 36
#define SMEM_BYTES (OFF_X + 128 * X_STRIDE * 4)   // 60416 -> 2 CTAs/SM

typedef unsigned long long ull;

// ---- packed fp32x2 helpers ----
__device__ __forceinline__ ull fma2(ull a, ull b, ull c) {
    ull d; asm("fma.rn.f32x2 %0,%1,%2,%3;" : "=l"(d) : "l"(a), "l"(b), "l"(c)); return d;
}
__device__ __forceinline__ ull mul2(ull a, ull b) {
    ull d; asm("mul.rn.f32x2 %0,%1,%2;" : "=l"(d) : "l"(a), "l"(b)); return d;
}
__device__ __forceinline__ void unpk(ull v, float& lo, float& hi) {
    asm("mov.b64 {%0,%1}, %2;" : "=f"(lo), "=f"(hi) : "l"(v));
}
__device__ __forceinline__ ull pk2(float lo, float hi) {
    ull v; asm("mov.b64 %0, {%1,%2};" : "=l"(v) : "f"(lo), "f"(hi)); return v;
}
__device__ __forceinline__ ull pkc(float c) {
    unsigned u = __float_as_uint(c); return ((ull)u << 32) | (ull)u;
}
__device__ __forceinline__ float frcp(float x) {
    float r; asm("rcp.approx.f32 %0,%1;" : "=f"(r) : "f"(x)); return r;
}
__device__ __forceinline__ unsigned smem_u32(const void* p) {
    unsigned a;
    asm("{.reg .u64 t; cvta.to.shared.u64 t, %1; cvt.u32.u64 %0, t;}" : "=r"(a) : "l"(p));
    return a;
}
__device__ __forceinline__ void cpasync16(const void* dst_smem, const void* src) {
    asm volatile("cp.async.ca.shared.global [%0], [%1], 16;"
                 :: "r"(smem_u32(dst_smem)), "l"(src));
}

// Exact-class GELU on a packed pair via A&S 7.1.28 (|erf err|<=3e-7, branch-free):
// gelu(x) = 0.5x + 0.5|x|(1 - d^-16), d = 1 + a1 z + ... + a6 z^6, z = |x|/sqrt2.
__device__ __forceinline__ ull gelu2(ull s) {
    const ull C_ISQ2 = pkc(0.70710678118654752f);
    ull z = mul2(s & 0x7FFFFFFF7FFFFFFFULL, C_ISQ2);
    ull d = fma2(z, pkc(0.0000430638f), pkc(0.0002765672f));
    d = fma2(z, d, pkc(0.0001520143f));
    d = fma2(z, d, pkc(0.0092705272f));
    d = fma2(z, d, pkc(0.0422820123f));
    d = fma2(z, d, pkc(0.0705230784f));
    d = fma2(z, d, pkc(1.0f));
    d = mul2(d, d); d = mul2(d, d); d = mul2(d, d); d = mul2(d, d);   // d^16
    float dl, dh; unpk(d, dl, dh);
    ull r = pk2(frcp(dl), frcp(dh));                                  // d^-16
    ull u = mul2(z, C_ISQ2);                                          // 0.5|x|
    ull w = fma2(r ^ 0x8000000080000000ULL, u, u);                    // u(1-r)
    return fma2(s, pkc(0.5f), w);
}

// packed f32 pair -> (bf16x2 hi, bf16x2 lo-residual)
__device__ __forceinline__ void splitpair(ull v, unsigned& hb, unsigned& lb) {
    float f0, f1; unpk(v, f0, f1);
    unsigned h;
    asm("cvt.rn.bf16x2.f32 %0, %1, %2;" : "=r"(h) : "f"(f1), "f"(f0));
    float a0 = __uint_as_float(h << 16);
    float a1 = __uint_as_float(h & 0xFFFF0000u);
    float r0 = f0 - a0, r1 = f1 - a1;
    unsigned l;
    asm("cvt.rn.bf16x2.f32 %0, %1, %2;" : "=r"(l) : "f"(r1), "f"(r0));
    hb = h; lb = l;
}

// D += A @ B; fp32 accum. NOT volatile: lets ptxas interleave.
__device__ __forceinline__ void mma16816(float d[4], const unsigned a[4],
                                         unsigned b0, unsigned b1) {
    asm("mma.sync.aligned.m16n8k16.row.col.f32.bf16.bf16.f32 "
        "{%0,%1,%2,%3},{%4,%5,%6,%7},{%8,%9},{%0,%1,%2,%3};"
        : "+f"(d[0]), "+f"(d[1]), "+f"(d[2]), "+f"(d[3])
        : "r"(a[0]), "r"(a[1]), "r"(a[2]), "r"(a[3]), "r"(b0), "r"(b1));
}

// B-fragment layout offset (W1/W2): 16B unit(o,t,p) = hi|lo
template<int KT>
__device__ __forceinline__ int woff16(int o, int k) {
    int t = k >> 4, kk = k & 15, pp = (kk & 7) >> 1, half = kk >> 3;
    int ts = t ^ (o & (KT - 1));
    return ((o * KT + ts) * 4 + pp) * 16 + half * 4 + (k & 1) * 2;
}

// A-fragment layout offset for W3 (hi; lo at +512)
__device__ __forceinline__ int woff_a3(int o, int k) {
    int mt = o >> 4, gg = o & 15, g = gg & 7, hi8 = gg >> 3;
    int t = k >> 4, kk = k & 15, pp = (kk & 7) >> 1, e = kk & 1, c8 = kk >> 3;
    int r = c8 * 2 + hi8;
    return (mt * 4 + t) * 1024 + ((g << 2) | pp) * 16 + (r << 2) + (e << 1);
}

// ---- one-shot fold kernel ----
__global__ void fold_kernel(
    const float* __restrict__ W1, const float* __restrict__ g1, const float* __restrict__ b1,
    const float* __restrict__ m1, const float* __restrict__ v1,
    const float* __restrict__ W2, const float* __restrict__ g2, const float* __restrict__ b2,
    const float* __restrict__ m2, const float* __restrict__ v2,
    const float* __restrict__ W3, const float* __restrict__ g3, const float* __restrict__ b3,
    const float* __restrict__ m3, const float* __restrict__ v3)
{
    int i = blockIdx.x * blockDim.x + threadIdx.x;
    if (i < 2048) {                               // W1 [64x32], B-frag layout
        int o = i >> 5, k = i & 31;
        float w = W1[i] * (g1[o] * rsqrtf(v1[o] + EPS));
        __nv_bfloat16 hi = __float2bfloat16(w);
        int off = woff16<2>(o, k);
        *(__nv_bfloat16*)(wbuf + off)     = hi;
        *(__nv_bfloat16*)(wbuf + off + 8) = __float2bfloat16(w - __bfloat162float(hi));
    } else if (i < 2048 + 4096) {                 // W2 [64x64], B-frag layout
        int j = i - 2048, o = j >> 6, k = j & 63;
        float w = W2[j] * (g2[o] * rsqrtf(v2[o] + EPS));
        __nv_bfloat16 hi = __float2bfloat16(w);
        int off = 8192 + woff16<4>(o, k);
        *(__nv_bfloat16*)(wbuf + off)     = hi;
        *(__nv_bfloat16*)(wbuf + off + 8) = __float2bfloat16(w - __bfloat162float(hi));
    } else if (i < 2048 + 8192) {                 // W3 [64x64], A-frag layout
        int j = i - 6144, o = j >> 6, k = j & 63;
        float w = W3[j] * (g3[o] * rsqrtf(v3[o] + EPS));
        __nv_bfloat16 hi = __float2bfloat16(w);
        int off = 24576 + woff_a3(o, k);
        *(__nv_bfloat16*)(wbuf + off)       = hi;
        *(__nv_bfloat16*)(wbuf + off + 512) = __float2bfloat16(w - __bfloat162float(hi));
    }
    if (i < 64) {
        bbuf[i]       = b1[i] - m1[i] * (g1[i] * rsqrtf(v1[i] + EPS));
        bbuf[64 + i]  = b2[i] - m2[i] * (g2[i] * rsqrtf(v2[i] + EPS));
        bbuf[128 + i] = b3[i] - m3[i] * (g3[i] * rsqrtf(v3[i] + EPS));
    }
    asm volatile("griddepcontrol.launch_dependents;");
}

// Stages 1-2 (act as A): D[8][4] = bias + (Ah+Al)@(Wh+Wl)^T, dropping lo*lo.
template<int KT>
__device__ __forceinline__ void run_stage(const char* w, const float* bias,
                                          unsigned Ah[4][4], unsigned Al[4][4],
                                          float D[8][4], int g, int p) {
    #pragma unroll
    for (int j = 0; j < 8; ++j) {
        float b0, b1;
        unpk(*(const ull*)(bias + 8 * j + 2 * p), b0, b1);
        D[j][0] = b0; D[j][1] = b1; D[j][2] = b0; D[j][3] = b1;
        int o = 8 * j + g;
        #pragma unroll
        for (int t = 0; t < KT; ++t) {
            int ts = t ^ (o & (KT - 1));
            int unit = (o * KT + ts) * 4 + p;
            ulonglong2 wv = *(const ulonglong2*)(w + unit * 16);   // one LDS.128: hi|lo
            unsigned bh0 = (unsigned)wv.x, bh1 = (unsigned)(wv.x >> 32);
            unsigned bl0 = (unsigned)wv.y, bl1 = (unsigned)(wv.y >> 32);
            mma16816(D[j], Ah[t], bh0, bh1);   // hi*hi
            mma16816(D[j], Ah[t], bl0, bl1);   // hi*lo
            mma16816(D[j], Al[t], bh0, bh1);   // lo*hi
        }
    }
}

// gelu + re-split into next stage's A fragments
__device__ __forceinline__ void epilogue_mid(float D[8][4],
                                             unsigned Ah[4][4], unsigned Al[4][4]) {
    #pragma unroll
    for (int j = 0; j < 8; ++j) {
        int t = j >> 1;
        int rb = (j & 1) ? 2 : 0;
        ull v0 = gelu2(pk2(D[j][0], D[j][1]));
        ull v1 = gelu2(pk2(D[j][2], D[j][3]));
        splitpair(v0, Ah[t][rb],     Al[t][rb]);
        splitpair(v1, Ah[t][rb + 1], Al[t][rb + 1]);
    }
}

// Full 3-stage pipeline for one 128-pt tile; Ah/Al hold stage-1 fragments on entry.
__device__ __forceinline__ void process_tile(
    const char* sw, const float* sbias,
    unsigned Ah[4][4], unsigned Al[4][4],
    float* __restrict__ out, int pbase, int lane, int wid, int g, int p)
{
    float D[8][4];
    run_stage<2>(sw,        sbias,      Ah, Al, D, g, p);
    epilogue_mid(D, Ah, Al);
    run_stage<4>(sw + 8192, sbias + 64, Ah, Al, D, g, p);
    epilogue_mid(D, Ah, Al);

    // Stage 3: W3 as A, activations reused as B-fragments (layout identity).
    float D3[4][2][4];
    #pragma unroll
    for (int mt = 0; mt < 4; ++mt) {
        float blo = sbias[128 + 16 * mt + g];
        float bhi = sbias[128 + 16 * mt + g + 8];
        #pragma unroll
        for (int nb = 0; nb < 2; ++nb) {
            D3[mt][nb][0] = blo; D3[mt][nb][1] = blo;
            D3[mt][nb][2] = bhi; D3[mt][nb][3] = bhi;
        }
        #pragma unroll
        for (int t = 0; t < 4; ++t) {
            const char* blk = sw + 24576 + (mt * 4 + t) * 1024 + lane * 16;
            uint4 whv = *(const uint4*)blk;            // hi a[4]
            uint4 wlv = *(const uint4*)(blk + 512);    // lo a[4]
            unsigned wh[4] = {whv.x, whv.y, whv.z, whv.w};
            unsigned wl[4] = {wlv.x, wlv.y, wlv.z, wlv.w};
            #pragma unroll
            for (int nb = 0; nb < 2; ++nb) {
                mma16816(D3[mt][nb], wh, Ah[t][nb], Ah[t][nb + 2]);   // hi*hi
                mma16816(D3[mt][nb], wh, Al[t][nb], Al[t][nb + 2]);   // hi*lo
                mma16816(D3[mt][nb], wl, Ah[t][nb], Ah[t][nb + 2]);   // lo*hi
            }
        }
    }

    // final: gelu -> STG.64 (adjacent points, same output channel)
    float* outp = out + (size_t)(pbase >> 10) * 65536 + (pbase & 1023) + wid * 16;
    #pragma unroll
    for (int mt = 0; mt < 4; ++mt) {
        #pragma unroll
        for (int nb = 0; nb < 2; ++nb) {
            ull v0 = gelu2(pk2(D3[mt][nb][0], D3[mt][nb][1]));
            ull v1 = gelu2(pk2(D3[mt][nb][2], D3[mt][nb][3]));
            float* a = outp + (size_t)(16 * mt + g) * 1024 + 8 * nb + 2 * p;
            *(ull*)a = v0;
            *(ull*)(a + 8 * 1024) = v1;
        }
    }
}

__global__ void __launch_bounds__(THREADS, 2) mlp_mma_kernel(
    const float* __restrict__ x, float* __restrict__ out)
{
    extern __shared__ char smem[];
    float* sbias = (float*)(smem + OFF_BIAS);
    char*  sw    = smem + OFF_W;
    float* sx    = (float*)(smem + OFF_X);

    const int tid = threadIdx.x;
    const int lane = tid & 31, wid = tid >> 5;   // warp = one 16-row m-tile
    const int g = lane >> 2, p = lane & 3;

    const int pbase0 = blockIdx.x * TILE_M;                  // tile A
    const int pbase1 = (blockIdx.x + NBLK2) * TILE_M;        // tile B

    // ---- PDL phase 1 (fold-independent): tile-A frags from GMEM + tile-B prefetch ----
    unsigned Ah[4][4], Al[4][4];
    {
        const float* xr = x + (size_t)(pbase0 + wid * 16 + g) * 32;   // row g; row g+8 = +256
        #pragma unroll
        for (int t = 0; t < 2; ++t) {
            int c0 = p * 2 + t * 16;
            splitpair(*(const ull*)(xr + c0),           Ah[t][0], Al[t][0]);
            splitpair(*(const ull*)(xr + 256 + c0),     Ah[t][1], Al[t][1]);
            splitpair(*(const ull*)(xr + c0 + 8),       Ah[t][2], Al[t][2]);
            splitpair(*(const ull*)(xr + 256 + c0 + 8), Ah[t][3], Al[t][3]);
        }
    }
    {
        // tile-B x: 128x32 f32 -> padded sx rows (stride 36), 4x16B per thread
        const float* xb = x + (size_t)pbase1 * 32;
        #pragma unroll
        for (int i = 0; i < 4; ++i) {
            int c = tid + i * THREADS;           // 16B-chunk id, 8 chunks/row
            int r = c >> 3, o4 = (c & 7) * 4;
            cpasync16(sx + r * X_STRIDE + o4, xb + r * 32 + o4);
        }
        asm volatile("cp.async.commit_group;");
    }

    // ---- PDL phase 2: wait for fold_kernel's weights, stage them ----
    asm volatile("griddepcontrol.wait;" ::: "memory");
    {
        const uint4* src = (const uint4*)wbuf;
        uint4* dst = (uint4*)sw;
        #pragma unroll
        for (int i = 0; i < 10; ++i) dst[tid + i * THREADS] = src[tid + i * THREADS];
        if (tid < 48) ((uint4*)sbias)[tid] = ((const uint4*)bbuf)[tid];
    }
    __syncthreads();

    // ---- tile A ----
    process_tile(sw, sbias, Ah, Al, out, pbase0, lane, wid, g, p);

    // ---- tile B: prefetched x -> fragments -> pipeline ----
    asm volatile("cp.async.wait_group 0;" ::: "memory");
    __syncthreads();
    {
        const float* xr = sx + (wid * 16 + g) * X_STRIDE;    // row g; row g+8 = +8*X_STRIDE
        #pragma unroll
        for (int t = 0; t < 2; ++t) {
            int c0 = p * 2 + t * 16;
            splitpair(*(const ull*)(xr + c0),                    Ah[t][0], Al[t][0]);
            splitpair(*(const ull*)(xr + 8 * X_STRIDE + c0),     Ah[t][1], Al[t][1]);
            splitpair(*(const ull*)(xr + c0 + 8),                Ah[t][2], Al[t][2]);
            splitpair(*(const ull*)(xr + 8 * X_STRIDE + c0 + 8), Ah[t][3], Al[t][3]);
        }
    }
    process_tile(sw, sbias, Ah, Al, out, pbase1, lane, wid, g, p);
}

extern "C" void kernel_launch(void* const* d_in, const int* in_sizes, int n_in,
                              void* d_out, int out_size)
{
    const float* x  = (const float*)d_in[0];
    const float* W1 = (const float*)d_in[1];
    const float* g1 = (const float*)d_in[2];
    const float* b1 = (const float*)d_in[3];
    const float* m1 = (const float*)d_in[4];
    const float* v1 = (const float*)d_in[5];
    const float* W2 = (const float*)d_in[6];
    const float* g2 = (const float*)d_in[7];
    const float* b2 = (const float*)d_in[8];
    const float* m2 = (const float*)d_in[9];
    const float* v2 = (const float*)d_in[10];
    const float* W3 = (const float*)d_in[11];
    const float* g3 = (const float*)d_in[12];
    const float* b3 = (const float*)d_in[13];
    const float* m3 = (const float*)d_in[14];
    const float* v3 = (const float*)d_in[15];
    float* out = (float*)d_out;

    fold_kernel<<<40, 256>>>(W1, g1, b1, m1, v1, W2, g2, b2, m2, v2, W3, g3, b3, m3, v3);

    cudaFuncSetAttribute(mlp_mma_kernel,
                         cudaFuncAttributeMaxDynamicSharedMemorySize, SMEM_BYTES);

    cudaLaunchConfig_t cfg = {};
    cfg.gridDim = dim3(NBLK2, 1, 1);
    cfg.blockDim = dim3(THREADS, 1, 1);
    cfg.dynamicSmemBytes = SMEM_BYTES;
    cfg.stream = 0;
    cudaLaunchAttribute attrs[1];
    attrs[0].id = cudaLaunchAttributeProgrammaticStreamSerialization;
    attrs[0].val.programmaticStreamSerializationAllowed = 1;
    cfg.attrs = attrs;
    cfg.numAttrs = 1;
    cudaLaunchKernelEx(&cfg, mlp_mma_kernel, x, out);
}

// round 14
// speedup vs baseline: 1.0195x; 1.0182x over previous
#include <cuda_runtime.h>
#include <cuda_bf16.h>

#define EPS      1e-5f
#define THREADS  256
#define TILE_M   128
#define NPTS     (64 * 1024)
#define NTILES   (NPTS / TILE_M)     // 512
#define NBLK2    (NTILES / 2)        // 256 persistent CTAs, 2 tiles each

// ---- pre-folded weights ----
// W1 @0 (8192B, KT=2) and W2 @8192 (16384B, KT=4): B-fragment layout,
//   16B unit(o,t,p) = [hi frag 8B | lo frag 8B], t XOR-swizzled.
// W3 @24576 (16384B): A-fragment layout, per (mt,t) 1KB block:
//   hi a[4] (16B) at lane*16, lo a[4] at +512.
__device__ __align__(16) char  wbuf[40960];
__device__ __align__(16) float bbuf[192];

// ---- dynamic SMEM layout (bytes) ----
#define OFF_BIAS 0                   // 192 f32 (pad to 1024)
#define OFF_W    1024                // 40960
#define OFF_X    41984               // tile-2 x staging: 128 rows x 36 f32
#define X_STRIDE 36
#define SMEM_BYTES (OFF_X + 128 * X_STRIDE * 4)   // 60416 -> 2 CTAs/SM

typedef unsigned long long ull;

// ---- packed fp32x2 helpers ----
__device__ __forceinline__ ull fma2(ull a, ull b, ull c) {
    ull d; asm("fma.rn.f32x2 %0,%1,%2,%3;" : "=l"(d) : "l"(a), "l"(b), "l"(c)); return d;
}
__device__ __forceinline__ ull mul2(ull a, ull b) {
    ull d; asm("mul.rn.f32x2 %0,%1,%2;" : "=l"(d) : "l"(a), "l"(b)); return d;
}
__device__ __forceinline__ void unpk(ull v, float& lo, float& hi) {
    asm("mov.b64 {%0,%1}, %2;" : "=f"(lo), "=f"(hi) : "l"(v));
}
__device__ __forceinline__ ull pk2(float lo, float hi) {
    ull v; asm("mov.b64 %0, {%1,%2};" : "=l"(v) : "f"(lo), "f"(hi)); return v;
}
__device__ __forceinline__ ull pkc(float c) {
    unsigned u = __float_as_uint(c); return ((ull)u << 32) | (ull)u;
}
__device__ __forceinline__ float frcp(float x) {
    float r; asm("rcp.approx.f32 %0,%1;" : "=f"(r) : "f"(x)); return r;
}
__device__ __forceinline__ unsigned smem_u32(const void* p) {
    unsigned a;
    asm("{.reg .u64 t; cvta.to.shared.u64 t, %1; cvt.u32.u64 %0, t;}" : "=r"(a) : "l"(p));
    return a;
}
__device__ __forceinline__ void cpasync16(const void* dst_smem, const void* src) {
    asm volatile("cp.async.ca.shared.global [%0], [%1], 16;"
                 :: "r"(smem_u32(dst_smem)), "l"(src));
}

// GELU on a packed pair via A&S 7.1.27 (deg-4, ^-4): erf(z) ~= 1 - d^-4,
// d = 1 + a1 z + a2 z^2 + a3 z^3 + a4 z^4, z>=0, |err|<=5e-4 abs.
// gelu(x) = 0.5x + 0.5|x|(1 - d^-4), z = |x|/sqrt2, 0.5|x| = z/sqrt2.
// ~13 ops/pair vs 18 for the deg-6 version; norm-rel error ~1e-4 vs 1e-3 budget.
__device__ __forceinline__ ull gelu2(ull s) {
    const ull C_ISQ2 = pkc(0.70710678118654752f);
    ull z = mul2(s & 0x7FFFFFFF7FFFFFFFULL, C_ISQ2);
    ull d = fma2(z, pkc(0.078108f), pkc(0.000972f));
    d = fma2(z, d, pkc(0.230389f));
    d = fma2(z, d, pkc(0.278393f));
    d = fma2(z, d, pkc(1.0f));
    d = mul2(d, d); d = mul2(d, d);                    // d^4
    float dl, dh; unpk(d, dl, dh);
    ull r = pk2(frcp(dl), frcp(dh));                   // d^-4
    ull u = mul2(z, C_ISQ2);                           // 0.5|x|
    ull w = fma2(r ^ 0x8000000080000000ULL, u, u);     // u(1-r)
    return fma2(s, pkc(0.5f), w);                      // + 0.5x
}

// packed f32 pair -> (bf16x2 hi, bf16x2 lo-residual)
__device__ __forceinline__ void splitpair(ull v, unsigned& hb, unsigned& lb) {
    float f0, f1; unpk(v, f0, f1);
    unsigned h;
    asm("cvt.rn.bf16x2.f32 %0, %1, %2;" : "=r"(h) : "f"(f1), "f"(f0));
    float a0 = __uint_as_float(h << 16);
    float a1 = __uint_as_float(h & 0xFFFF0000u);
    float r0 = f0 - a0, r1 = f1 - a1;
    unsigned l;
    asm("cvt.rn.bf16x2.f32 %0, %1, %2;" : "=r"(l) : "f"(r1), "f"(r0));
    hb = h; lb = l;
}

// D += A @ B; fp32 accum. NOT volatile: lets ptxas interleave.
__device__ __forceinline__ void mma16816(float d[4], const unsigned a[4],
                                         unsigned b0, unsigned b1) {
    asm("mma.sync.aligned.m16n8k16.row.col.f32.bf16.bf16.f32 "
        "{%0,%1,%2,%3},{%4,%5,%6,%7},{%8,%9},{%0,%1,%2,%3};"
        : "+f"(d[0]), "+f"(d[1]), "+f"(d[2]), "+f"(d[3])
        : "r"(a[0]), "r"(a[1]), "r"(a[2]), "r"(a[3]), "r"(b0), "r"(b1));
}

// B-fragment layout offset (W1/W2): 16B unit(o,t,p) = hi|lo
template<int KT>
__device__ __forceinline__ int woff16(int o, int k) {
    int t = k >> 4, kk = k & 15, pp = (kk & 7) >> 1, half = kk >> 3;
    int ts = t ^ (o & (KT - 1));
    return ((o * KT + ts) * 4 + pp) * 16 + half * 4 + (k & 1) * 2;
}

// A-fragment layout offset for W3 (hi; lo at +512)
__device__ __forceinline__ int woff_a3(int o, int k) {
    int mt = o >> 4, gg = o & 15, g = gg & 7, hi8 = gg >> 3;
    int t = k >> 4, kk = k & 15, pp = (kk & 7) >> 1, e = kk & 1, c8 = kk >> 3;
    int r = c8 * 2 + hi8;
    return (mt * 4 + t) * 1024 + ((g << 2) | pp) * 16 + (r << 2) + (e << 1);
}

// ---- one-shot fold kernel ----
__global__ void fold_kernel(
    const float* __restrict__ W1, const float* __restrict__ g1, const float* __restrict__ b1,
    const float* __restrict__ m1, const float* __restrict__ v1,
    const float* __restrict__ W2, const float* __restrict__ g2, const float* __restrict__ b2,
    const float* __restrict__ m2, const float* __restrict__ v2,
    const float* __restrict__ W3, const float* __restrict__ g3, const float* __restrict__ b3,
    const float* __restrict__ m3, const float* __restrict__ v3)
{
    int i = blockIdx.x * blockDim.x + threadIdx.x;
    if (i < 2048) {                               // W1 [64x32], B-frag layout
        int o = i >> 5, k = i & 31;
        float w = W1[i] * (g1[o] * rsqrtf(v1[o] + EPS));
        __nv_bfloat16 hi = __float2bfloat16(w);
        int off = woff16<2>(o, k);
        *(__nv_bfloat16*)(wbuf + off)     = hi;
        *(__nv_bfloat16*)(wbuf + off + 8) = __float2bfloat16(w - __bfloat162float(hi));
    } else if (i < 2048 + 4096) {                 // W2 [64x64], B-frag layout
        int j = i - 2048, o = j >> 6, k = j & 63;
        float w = W2[j] * (g2[o] * rsqrtf(v2[o] + EPS));
        __nv_bfloat16 hi = __float2bfloat16(w);
        int off = 8192 + woff16<4>(o, k);
        *(__nv_bfloat16*)(wbuf + off)     = hi;
        *(__nv_bfloat16*)(wbuf + off + 8) = __float2bfloat16(w - __bfloat162float(hi));
    } else if (i < 2048 + 8192) {                 // W3 [64x64], A-frag layout
        int j = i - 6144, o = j >> 6, k = j & 63;
        float w = W3[j] * (g3[o] * rsqrtf(v3[o] + EPS));
        __nv_bfloat16 hi = __float2bfloat16(w);
        int off = 24576 + woff_a3(o, k);
        *(__nv_bfloat16*)(wbuf + off)       = hi;
        *(__nv_bfloat16*)(wbuf + off + 512) = __float2bfloat16(w - __bfloat162float(hi));
    }
    if (i < 64) {
        bbuf[i]       = b1[i] - m1[i] * (g1[i] * rsqrtf(v1[i] + EPS));
        bbuf[64 + i]  = b2[i] - m2[i] * (g2[i] * rsqrtf(v2[i] + EPS));
        bbuf[128 + i] = b3[i] - m3[i] * (g3[i] * rsqrtf(v3[i] + EPS));
    }
    asm volatile("griddepcontrol.launch_dependents;");
}

// Stages 1-2 (act as A): D[8][4] = bias + (Ah+Al)@(Wh+Wl)^T, dropping lo*lo.
template<int KT>
__device__ __forceinline__ void run_stage(const char* w, const float* bias,
                                          unsigned Ah[4][4], unsigned Al[4][4],
                                          float D[8][4], int g, int p) {
    #pragma unroll
    for (int j = 0; j < 8; ++j) {
        float b0, b1;
        unpk(*(const ull*)(bias + 8 * j + 2 * p), b0, b1);
        D[j][0] = b0; D[j][1] = b1; D[j][2] = b0; D[j][3] = b1;
        int o = 8 * j + g;
        #pragma unroll
        for (int t = 0; t < KT; ++t) {
            int ts = t ^ (o & (KT - 1));
            int unit = (o * KT + ts) * 4 + p;
            ulonglong2 wv = *(const ulonglong2*)(w + unit * 16);   // one LDS.128: hi|lo
            unsigned bh0 = (unsigned)wv.x, bh1 = (unsigned)(wv.x >> 32);
            unsigned bl0 = (unsigned)wv.y, bl1 = (unsigned)(wv.y >> 32);
            mma16816(D[j], Ah[t], bh0, bh1);   // hi*hi
            mma16816(D[j], Ah[t], bl0, bl1);   // hi*lo
            mma16816(D[j], Al[t], bh0, bh1);   // lo*hi
        }
    }
}

// gelu + re-split into next stage's A fragments
__device__ __forceinline__ void epilogue_mid(float D[8][4],
                                             unsigned Ah[4][4], unsigned Al[4][4]) {
    #pragma unroll
    for (int j = 0; j < 8; ++j) {
        int t = j >> 1;
        int rb = (j & 1) ? 2 : 0;
        ull v0 = gelu2(pk2(D[j][0], D[j][1]));
        ull v1 = gelu2(pk2(D[j][2], D[j][3]));
        splitpair(v0, Ah[t][rb],     Al[t][rb]);
        splitpair(v1, Ah[t][rb + 1], Al[t][rb + 1]);
    }
}

// Full 3-stage pipeline for one 128-pt tile; Ah/Al hold stage-1 fragments on entry.
__device__ __forceinline__ void process_tile(
    const char* sw, const float* sbias,
    unsigned Ah[4][4], unsigned Al[4][4],
    float* __restrict__ out, int pbase, int lane, int wid, int g, int p)
{
    float D[8][4];
    run_stage<2>(sw,        sbias,      Ah, Al, D, g, p);
    epilogue_mid(D, Ah, Al);
    run_stage<4>(sw + 8192, sbias + 64, Ah, Al, D, g, p);
    epilogue_mid(D, Ah, Al);

    // Stage 3: W3 as A, activations reused as B-fragments (layout identity).
    float D3[4][2][4];
    #pragma unroll
    for (int mt = 0; mt < 4; ++mt) {
        float blo = sbias[128 + 16 * mt + g];
        float bhi = sbias[128 + 16 * mt + g + 8];
        #pragma unroll
        for (int nb = 0; nb < 2; ++nb) {
            D3[mt][nb][0] = blo; D3[mt][nb][1] = blo;
            D3[mt][nb][2] = bhi; D3[mt][nb][3] = bhi;
        }
        #pragma unroll
        for (int t = 0; t < 4; ++t) {
            const char* blk = sw + 24576 + (mt * 4 + t) * 1024 + lane * 16;
            uint4 whv = *(const uint4*)blk;            // hi a[4]
            uint4 wlv = *(const uint4*)(blk + 512);    // lo a[4]
            unsigned wh[4] = {whv.x, whv.y, whv.z, whv.w};
            unsigned wl[4] = {wlv.x, wlv.y, wlv.z, wlv.w};
            #pragma unroll
            for (int nb = 0; nb < 2; ++nb) {
                mma16816(D3[mt][nb], wh, Ah[t][nb], Ah[t][nb + 2]);   // hi*hi
                mma16816(D3[mt][nb], wh, Al[t][nb], Al[t][nb + 2]);   // hi*lo
                mma16816(D3[mt][nb], wl, Ah[t][nb], Ah[t][nb + 2]);   // lo*hi
            }
        }
    }

    // final: gelu -> STG.64 (adjacent points, same output channel)
    float* outp = out + (size_t)(pbase >> 10) * 65536 + (pbase & 1023) + wid * 16;
    #pragma unroll
    for (int mt = 0; mt < 4; ++mt) {
        #pragma unroll
        for (int nb = 0; nb < 2; ++nb) {
            ull v0 = gelu2(pk2(D3[mt][nb][0], D3[mt][nb][1]));
            ull v1 = gelu2(pk2(D3[mt][nb][2], D3[mt][nb][3]));
            float* a = outp + (size_t)(16 * mt + g) * 1024 + 8 * nb + 2 * p;
            *(ull*)a = v0;
            *(ull*)(a + 8 * 1024) = v1;
        }
    }
}

__global__ void __launch_bounds__(THREADS, 2) mlp_mma_kernel(
    const float* __restrict__ x, float* __restrict__ out)
{
    extern __shared__ char smem[];
    float* sbias = (float*)(smem + OFF_BIAS);
    char*  sw    = smem + OFF_W;
    float* sx    = (float*)(smem + OFF_X);

    const int tid = threadIdx.x;
    const int lane = tid & 31, wid = tid >> 5;   // warp = one 16-row m-tile
    const int g = lane >> 2, p = lane & 3;

    const int pbase0 = blockIdx.x * TILE_M;                  // tile A
    const int pbase1 = (blockIdx.x + NBLK2) * TILE_M;        // tile B

    // ---- PDL phase 1 (fold-independent): tile-A frags from GMEM + tile-B prefetch ----
    unsigned Ah[4][4], Al[4][4];
    {
        const float* xr = x + (size_t)(pbase0 + wid * 16 + g) * 32;   // row g; row g+8 = +256
        #pragma unroll
        for (int t = 0; t < 2; ++t) {
            int c0 = p * 2 + t * 16;
            splitpair(*(const ull*)(xr + c0),           Ah[t][0], Al[t][0]);
            splitpair(*(const ull*)(xr + 256 + c0),     Ah[t][1], Al[t][1]);
            splitpair(*(const ull*)(xr + c0 + 8),       Ah[t][2], Al[t][2]);
            splitpair(*(const ull*)(xr + 256 + c0 + 8), Ah[t][3], Al[t][3]);
        }
    }
    {
        // tile-B x: 128x32 f32 -> padded sx rows (stride 36), 4x16B per thread
        const float* xb = x + (size_t)pbase1 * 32;
        #pragma unroll
        for (int i = 0; i < 4; ++i) {
            int c = tid + i * THREADS;           // 16B-chunk id, 8 chunks/row
            int r = c >> 3, o4 = (c & 7) * 4;
            cpasync16(sx + r * X_STRIDE + o4, xb + r * 32 + o4);
        }
        asm volatile("cp.async.commit_group;");
    }

    // ---- PDL phase 2: wait for fold_kernel's weights, stage them ----
    asm volatile("griddepcontrol.wait;" ::: "memory");
    {
        const uint4* src = (const uint4*)wbuf;
        uint4* dst = (uint4*)sw;
        #pragma unroll
        for (int i = 0; i < 10; ++i) dst[tid + i * THREADS] = src[tid + i * THREADS];
        if (tid < 48) ((uint4*)sbias)[tid] = ((const uint4*)bbuf)[tid];
    }
    __syncthreads();

    // ---- tile A ----
    process_tile(sw, sbias, Ah, Al, out, pbase0, lane, wid, g, p);

    // ---- tile B: prefetched x -> fragments -> pipeline ----
    asm volatile("cp.async.wait_group 0;" ::: "memory");
    __syncthreads();
    {
        const float* xr = sx + (wid * 16 + g) * X_STRIDE;    // row g; row g+8 = +8*X_STRIDE
        #pragma unroll
        for (int t = 0; t < 2; ++t) {
            int c0 = p * 2 + t * 16;
            splitpair(*(const ull*)(xr + c0),                    Ah[t][0], Al[t][0]);
            splitpair(*(const ull*)(xr + 8 * X_STRIDE + c0),     Ah[t][1], Al[t][1]);
            splitpair(*(const ull*)(xr + c0 + 8),                Ah[t][2], Al[t][2]);
            splitpair(*(const ull*)(xr + 8 * X_STRIDE + c0 + 8), Ah[t][3], Al[t][3]);
        }
    }
    process_tile(sw, sbias, Ah, Al, out, pbase1, lane, wid, g, p);
}

extern "C" void kernel_launch(void* const* d_in, const int* in_sizes, int n_in,
                              void* d_out, int out_size)
{
    const float* x  = (const float*)d_in[0];
    const float* W1 = (const float*)d_in[1];
    const float* g1 = (const float*)d_in[2];
    const float* b1 = (const float*)d_in[3];
    const float* m1 = (const float*)d_in[4];
    const float* v1 = (const float*)d_in[5];
    const float* W2 = (const float*)d_in[6];
    const float* g2 = (const float*)d_in[7];
    const float* b2 = (const float*)d_in[8];
    const float* m2 = (const float*)d_in[9];
    const float* v2 = (const float*)d_in[10];
    const float* W3 = (const float*)d_in[11];
    const float* g3 = (const float*)d_in[12];
    const float* b3 = (const float*)d_in[13];
    const float* m3 = (const float*)d_in[14];
    const float* v3 = (const float*)d_in[15];
    float* out = (float*)d_out;

    fold_kernel<<<40, 256>>>(W1, g1, b1, m1, v1, W2, g2, b2, m2, v2, W3, g3, b3, m3, v3);

    cudaFuncSetAttribute(mlp_mma_kernel,
                         cudaFuncAttributeMaxDynamicSharedMemorySize, SMEM_BYTES);

    cudaLaunchConfig_t cfg = {};
    cfg.gridDim = dim3(NBLK2, 1, 1);
    cfg.blockDim = dim3(THREADS, 1, 1);
    cfg.dynamicSmemBytes = SMEM_BYTES;
    cfg.stream = 0;
    cudaLaunchAttribute attrs[1];
    attrs[0].id = cudaLaunchAttributeProgrammaticStreamSerialization;
    attrs[0].val.programmaticStreamSerializationAllowed = 1;
    cfg.attrs = attrs;
    cfg.numAttrs = 1;
    cudaLaunchKernelEx(&cfg, mlp_mma_kernel, x, out);
}

// round 15
// speedup vs baseline: 1.0798x; 1.0591x over previous
#include <cuda_runtime.h>
#include <cuda_bf16.h>

#define EPS      1e-5f
#define THREADS  128                 // 4 warps x m16 rows
#define TILE_M   64
#define NPTS     (64 * 1024)
#define NBLK     (NPTS / TILE_M)     // 1024 CTAs -> per-SM tile tail ~1%

// ---- pre-folded weights ----
// W1 @0 (8192B, KT=2) and W2 @8192 (16384B, KT=4): B-fragment layout,
//   16B unit(o,t,p) = [hi frag 8B | lo frag 8B], t XOR-swizzled.
// W3 @24576 (16384B): A-fragment layout, per (mt,t) 1KB block:
//   hi a[4] (16B) at lane*16, lo a[4] at +512.
// Padded to 43008 = 21*128*16 so the SMEM copy is a flat 21-iteration loop.
__device__ __align__(16) char  wbuf[43008];
__device__ __align__(16) float bbuf[192];

// ---- dynamic SMEM layout (bytes) ----
#define OFF_BIAS 0                   // 192 f32 (pad to 1024)
#define OFF_W    1024
#define SMEM_BYTES (OFF_W + 43008)   // 44032 -> 4 CTAs/SM (176KB of 228KB)

typedef unsigned long long ull;

// ---- packed fp32x2 helpers ----
__device__ __forceinline__ ull fma2(ull a, ull b, ull c) {
    ull d; asm("fma.rn.f32x2 %0,%1,%2,%3;" : "=l"(d) : "l"(a), "l"(b), "l"(c)); return d;
}
__device__ __forceinline__ ull mul2(ull a, ull b) {
    ull d; asm("mul.rn.f32x2 %0,%1,%2;" : "=l"(d) : "l"(a), "l"(b)); return d;
}
__device__ __forceinline__ void unpk(ull v, float& lo, float& hi) {
    asm("mov.b64 {%0,%1}, %2;" : "=f"(lo), "=f"(hi) : "l"(v));
}
__device__ __forceinline__ ull pk2(float lo, float hi) {
    ull v; asm("mov.b64 %0, {%1,%2};" : "=l"(v) : "f"(lo), "f"(hi)); return v;
}
__device__ __forceinline__ ull pkc(float c) {
    unsigned u = __float_as_uint(c); return ((ull)u << 32) | (ull)u;
}
__device__ __forceinline__ float frcp(float x) {
    float r; asm("rcp.approx.f32 %0,%1;" : "=f"(r) : "f"(x)); return r;
}

// GELU on a packed pair via A&S 7.1.27 (deg-4, ^-4): |erf err|<=5e-4 abs.
// Measured overall rel_err 4.4e-4 vs 1e-3 budget (deterministic fixed-seed inputs).
__device__ __forceinline__ ull gelu2(ull s) {
    const ull C_ISQ2 = pkc(0.70710678118654752f);
    ull z = mul2(s & 0x7FFFFFFF7FFFFFFFULL, C_ISQ2);
    ull d = fma2(z, pkc(0.078108f), pkc(0.000972f));
    d = fma2(z, d, pkc(0.230389f));
    d = fma2(z, d, pkc(0.278393f));
    d = fma2(z, d, pkc(1.0f));
    d = mul2(d, d); d = mul2(d, d);                    // d^4
    float dl, dh; unpk(d, dl, dh);
    ull r = pk2(frcp(dl), frcp(dh));                   // d^-4
    ull u = mul2(z, C_ISQ2);                           // 0.5|x|
    ull w = fma2(r ^ 0x8000000080000000ULL, u, u);     // u(1-r)
    return fma2(s, pkc(0.5f), w);                      // + 0.5x
}

// packed f32 pair -> (bf16x2 hi, bf16x2 lo-residual)
__device__ __forceinline__ void splitpair(ull v, unsigned& hb, unsigned& lb) {
    float f0, f1; unpk(v, f0, f1);
    unsigned h;
    asm("cvt.rn.bf16x2.f32 %0, %1, %2;" : "=r"(h) : "f"(f1), "f"(f0));
    float a0 = __uint_as_float(h << 16);
    float a1 = __uint_as_float(h & 0xFFFF0000u);
    float r0 = f0 - a0, r1 = f1 - a1;
    unsigned l;
    asm("cvt.rn.bf16x2.f32 %0, %1, %2;" : "=r"(l) : "f"(r1), "f"(r0));
    hb = h; lb = l;
}

// D += A @ B; fp32 accum. NOT volatile: lets ptxas interleave.
__device__ __forceinline__ void mma16816(float d[4], const unsigned a[4],
                                         unsigned b0, unsigned b1) {
    asm("mma.sync.aligned.m16n8k16.row.col.f32.bf16.bf16.f32 "
        "{%0,%1,%2,%3},{%4,%5,%6,%7},{%8,%9},{%0,%1,%2,%3};"
        : "+f"(d[0]), "+f"(d[1]), "+f"(d[2]), "+f"(d[3])
        : "r"(a[0]), "r"(a[1]), "r"(a[2]), "r"(a[3]), "r"(b0), "r"(b1));
}

// B-fragment layout offset (W1/W2): 16B unit(o,t,p) = hi|lo
template<int KT>
__device__ __forceinline__ int woff16(int o, int k) {
    int t = k >> 4, kk = k & 15, pp = (kk & 7) >> 1, half = kk >> 3;
    int ts = t ^ (o & (KT - 1));
    return ((o * KT + ts) * 4 + pp) * 16 + half * 4 + (k & 1) * 2;
}

// A-fragment layout offset for W3 (hi; lo at +512)
__device__ __forceinline__ int woff_a3(int o, int k) {
    int mt = o >> 4, gg = o & 15, g = gg & 7, hi8 = gg >> 3;
    int t = k >> 4, kk = k & 15, pp = (kk & 7) >> 1, e = kk & 1, c8 = kk >> 3;
    int r = c8 * 2 + hi8;
    return (mt * 4 + t) * 1024 + ((g << 2) | pp) * 16 + (r << 2) + (e << 1);
}

// ---- one-shot fold kernel ----
__global__ void fold_kernel(
    const float* __restrict__ W1, const float* __restrict__ g1, const float* __restrict__ b1,
    const float* __restrict__ m1, const float* __restrict__ v1,
    const float* __restrict__ W2, const float* __restrict__ g2, const float* __restrict__ b2,
    const float* __restrict__ m2, const float* __restrict__ v2,
    const float* __restrict__ W3, const float* __restrict__ g3, const float* __restrict__ b3,
    const float* __restrict__ m3, const float* __restrict__ v3)
{
    int i = blockIdx.x * blockDim.x + threadIdx.x;
    if (i < 2048) {                               // W1 [64x32], B-frag layout
        int o = i >> 5, k = i & 31;
        float w = W1[i] * (g1[o] * rsqrtf(v1[o] + EPS));
        __nv_bfloat16 hi = __float2bfloat16(w);
        int off = woff16<2>(o, k);
        *(__nv_bfloat16*)(wbuf + off)     = hi;
        *(__nv_bfloat16*)(wbuf + off + 8) = __float2bfloat16(w - __bfloat162float(hi));
    } else if (i < 2048 + 4096) {                 // W2 [64x64], B-frag layout
        int j = i - 2048, o = j >> 6, k = j & 63;
        float w = W2[j] * (g2[o] * rsqrtf(v2[o] + EPS));
        __nv_bfloat16 hi = __float2bfloat16(w);
        int off = 8192 + woff16<4>(o, k);
        *(__nv_bfloat16*)(wbuf + off)     = hi;
        *(__nv_bfloat16*)(wbuf + off + 8) = __float2bfloat16(w - __bfloat162float(hi));
    } else if (i < 2048 + 8192) {                 // W3 [64x64], A-frag layout
        int j = i - 6144, o = j >> 6, k = j & 63;
        float w = W3[j] * (g3[o] * rsqrtf(v3[o] + EPS));
        __nv_bfloat16 hi = __float2bfloat16(w);
        int off = 24576 + woff_a3(o, k);
        *(__nv_bfloat16*)(wbuf + off)       = hi;
        *(__nv_bfloat16*)(wbuf + off + 512) = __float2bfloat16(w - __bfloat162float(hi));
    }
    if (i < 64) {
        bbuf[i]       = b1[i] - m1[i] * (g1[i] * rsqrtf(v1[i] + EPS));
        bbuf[64 + i]  = b2[i] - m2[i] * (g2[i] * rsqrtf(v2[i] + EPS));
        bbuf[128 + i] = b3[i] - m3[i] * (g3[i] * rsqrtf(v3[i] + EPS));
    }
    asm volatile("griddepcontrol.launch_dependents;");
}

// Stages 1-2 (act as A): D[8][4] = bias + (Ah+Al)@(Wh+Wl)^T, dropping lo*lo.
template<int KT>
__device__ __forceinline__ void run_stage(const char* w, const float* bias,
                                          unsigned Ah[4][4], unsigned Al[4][4],
                                          float D[8][4], int g, int p) {
    #pragma unroll
    for (int j = 0; j < 8; ++j) {
        float b0, b1;
        unpk(*(const ull*)(bias + 8 * j + 2 * p), b0, b1);
        D[j][0] = b0; D[j][1] = b1; D[j][2] = b0; D[j][3] = b1;
        int o = 8 * j + g;
        #pragma unroll
        for (int t = 0; t < KT; ++t) {
            int ts = t ^ (o & (KT - 1));
            int unit = (o * KT + ts) * 4 + p;
            ulonglong2 wv = *(const ulonglong2*)(w + unit * 16);   // one LDS.128: hi|lo
            unsigned bh0 = (unsigned)wv.x, bh1 = (unsigned)(wv.x >> 32);
            unsigned bl0 = (unsigned)wv.y, bl1 = (unsigned)(wv.y >> 32);
            mma16816(D[j], Ah[t], bh0, bh1);   // hi*hi
            mma16816(D[j], Ah[t], bl0, bl1);   // hi*lo
            mma16816(D[j], Al[t], bh0, bh1);   // lo*hi
        }
    }
}

// gelu + re-split into next stage's A fragments
__device__ __forceinline__ void epilogue_mid(float D[8][4],
                                             unsigned Ah[4][4], unsigned Al[4][4]) {
    #pragma unroll
    for (int j = 0; j < 8; ++j) {
        int t = j >> 1;
        int rb = (j & 1) ? 2 : 0;
        ull v0 = gelu2(pk2(D[j][0], D[j][1]));
        ull v1 = gelu2(pk2(D[j][2], D[j][3]));
        splitpair(v0, Ah[t][rb],     Al[t][rb]);
        splitpair(v1, Ah[t][rb + 1], Al[t][rb + 1]);
    }
}

__global__ void __launch_bounds__(THREADS, 4) mlp_mma_kernel(
    const float* __restrict__ x, float* __restrict__ out)
{
    extern __shared__ char smem[];
    float* sbias = (float*)(smem + OFF_BIAS);
    char*  sw    = smem + OFF_W;

    const int tid = threadIdx.x;
    const int lane = tid & 31, wid = tid >> 5;   // warp = one 16-row m-tile (4 warps = 64 rows)
    const int g = lane >> 2, p = lane & 3;

    const int pbase = blockIdx.x * TILE_M;

    // ---- PDL phase 1 (fold-independent): A fragments straight from GMEM ----
    unsigned Ah[4][4], Al[4][4];
    {
        const float* xr = x + (size_t)(pbase + wid * 16 + g) * 32;   // row g; row g+8 = +256
        #pragma unroll
        for (int t = 0; t < 2; ++t) {
            int c0 = p * 2 + t * 16;
            splitpair(*(const ull*)(xr + c0),           Ah[t][0], Al[t][0]);
            splitpair(*(const ull*)(xr + 256 + c0),     Ah[t][1], Al[t][1]);
            splitpair(*(const ull*)(xr + c0 + 8),       Ah[t][2], Al[t][2]);
            splitpair(*(const ull*)(xr + 256 + c0 + 8), Ah[t][3], Al[t][3]);
        }
    }

    // ---- PDL phase 2: wait for fold_kernel's weights, stage them (flat 21x copy) ----
    asm volatile("griddepcontrol.wait;" ::: "memory");
    {
        const uint4* src = (const uint4*)wbuf;
        uint4* dst = (uint4*)sw;
        #pragma unroll
        for (int i = 0; i < 21; ++i) dst[tid + i * THREADS] = src[tid + i * THREADS];
        if (tid < 48) ((uint4*)sbias)[tid] = ((const uint4*)bbuf)[tid];
    }
    __syncthreads();

    float D[8][4];
    run_stage<2>(sw,        sbias,      Ah, Al, D, g, p);
    epilogue_mid(D, Ah, Al);
    run_stage<4>(sw + 8192, sbias + 64, Ah, Al, D, g, p);
    epilogue_mid(D, Ah, Al);

    // Stage 3: W3 as A, activations reused as B-fragments (layout identity).
    float D3[4][2][4];
    #pragma unroll
    for (int mt = 0; mt < 4; ++mt) {
        float blo = sbias[128 + 16 * mt + g];
        float bhi = sbias[128 + 16 * mt + g + 8];
        #pragma unroll
        for (int nb = 0; nb < 2; ++nb) {
            D3[mt][nb][0] = blo; D3[mt][nb][1] = blo;
            D3[mt][nb][2] = bhi; D3[mt][nb][3] = bhi;
        }
        #pragma unroll
        for (int t = 0; t < 4; ++t) {
            const char* blk = sw + 24576 + (mt * 4 + t) * 1024 + lane * 16;
            uint4 whv = *(const uint4*)blk;            // hi a[4]
            uint4 wlv = *(const uint4*)(blk + 512);    // lo a[4]
            unsigned wh[4] = {whv.x, whv.y, whv.z, whv.w};
            unsigned wl[4] = {wlv.x, wlv.y, wlv.z, wlv.w};
            #pragma unroll
            for (int nb = 0; nb < 2; ++nb) {
                mma16816(D3[mt][nb], wh, Ah[t][nb], Ah[t][nb + 2]);   // hi*hi
                mma16816(D3[mt][nb], wh, Al[t][nb], Al[t][nb + 2]);   // hi*lo
                mma16816(D3[mt][nb], wl, Ah[t][nb], Ah[t][nb + 2]);   // lo*hi
            }
        }
    }

    // final: gelu -> STG.64 (adjacent points, same output channel)
    float* outp = out + (size_t)(pbase >> 10) * 65536 + (pbase & 1023) + wid * 16;
    #pragma unroll
    for (int mt = 0; mt < 4; ++mt) {
        #pragma unroll
        for (int nb = 0; nb < 2; ++nb) {
            ull v0 = gelu2(pk2(D3[mt][nb][0], D3[mt][nb][1]));
            ull v1 = gelu2(pk2(D3[mt][nb][2], D3[mt][nb][3]));
            float* a = outp + (size_t)(16 * mt + g) * 1024 + 8 * nb + 2 * p;
            *(ull*)a = v0;
            *(ull*)(a + 8 * 1024) = v1;
        }
    }
}

extern "C" void kernel_launch(void* const* d_in, const int* in_sizes, int n_in,
                              void* d_out, int out_size)
{
    const float* x  = (const float*)d_in[0];
    const float* W1 = (const float*)d_in[1];
    const float* g1 = (const float*)d_in[2];
    const float* b1 = (const float*)d_in[3];
    const float* m1 = (const float*)d_in[4];
    const float* v1 = (const float*)d_in[5];
    const float* W2 = (const float*)d_in[6];
    const float* g2 = (const float*)d_in[7];
    const float* b2 = (const float*)d_in[8];
    const float* m2 = (const float*)d_in[9];
    const float* v2 = (const float*)d_in[10];
    const float* W3 = (const float*)d_in[11];
    const float* g3 = (const float*)d_in[12];
    const float* b3 = (const float*)d_in[13];
    const float* m3 = (const float*)d_in[14];
    const float* v3 = (const float*)d_in[15];
    float* out = (float*)d_out;

    fold_kernel<<<40, 256>>>(W1, g1, b1, m1, v1, W2, g2, b2, m2, v2, W3, g3, b3, m3, v3);

    cudaFuncSetAttribute(mlp_mma_kernel,
                         cudaFuncAttributeMaxDynamicSharedMemorySize, SMEM_BYTES);

    cudaLaunchConfig_t cfg = {};
    cfg.gridDim = dim3(NBLK, 1, 1);
    cfg.blockDim = dim3(THREADS, 1, 1);
    cfg.dynamicSmemBytes = SMEM_BYTES;
    cfg.stream = 0;
    cudaLaunchAttribute attrs[1];
    attrs[0].id = cudaLaunchAttributeProgrammaticStreamSerialization;
    attrs[0].val.programmaticStreamSerializationAllowed = 1;
    cfg.attrs = attrs;
    cfg.numAttrs = 1;
    cudaLaunchKernelEx(&cfg, mlp_mma_kernel, x, out);
}

// round 16
// speedup vs baseline: 1.3149x; 1.2178x over previous
#include <cuda_runtime.h>
#include <cuda_fp16.h>

#define EPS      1e-5f
#define THREADS  128                 // 4 warps x m16 rows
#define TILE_M   64
#define NPTS     (64 * 1024)
#define NBLK     (NPTS / TILE_M)     // 1024 CTAs

// ---- pre-folded fp16 weights ----
// W1 @0 (4096B): B-frag layout, 16B unit(o,p) = [t0:b0,b1 | t1:b0,b1]
// W2 @4096 (8192B): 16B unit(o,tp,p) = [t=2tp:b0,b1 | t=2tp+1:b0,b1], tp XOR (o&1)
// W3 @12288 (8192B): A-frag layout, per (mt,t) 512B block: a[4] (16B) at lane*16
__device__ __align__(16) char  wbuf[20480];
__device__ __align__(16) float bbuf[192];

// ---- dynamic SMEM layout (bytes) ----
#define OFF_BIAS 0                   // 192 f32 (pad to 1024)
#define OFF_W    1024
#define SMEM_BYTES (OFF_W + 20480)   // 21504 -> 5 CTAs/SM (107.5KB)

typedef unsigned long long ull;

// ---- packed fp32x2 helpers ----
__device__ __forceinline__ ull fma2(ull a, ull b, ull c) {
    ull d; asm("fma.rn.f32x2 %0,%1,%2,%3;" : "=l"(d) : "l"(a), "l"(b), "l"(c)); return d;
}
__device__ __forceinline__ ull mul2(ull a, ull b) {
    ull d; asm("mul.rn.f32x2 %0,%1,%2;" : "=l"(d) : "l"(a), "l"(b)); return d;
}
__device__ __forceinline__ void unpk(ull v, float& lo, float& hi) {
    asm("mov.b64 {%0,%1}, %2;" : "=f"(lo), "=f"(hi) : "l"(v));
}
__device__ __forceinline__ ull pk2(float lo, float hi) {
    ull v; asm("mov.b64 %0, {%1,%2};" : "=l"(v) : "f"(lo), "f"(hi)); return v;
}
__device__ __forceinline__ ull pkc(float c) {
    unsigned u = __float_as_uint(c); return ((ull)u << 32) | (ull)u;
}
__device__ __forceinline__ float frcp(float x) {
    float r; asm("rcp.approx.f32 %0,%1;" : "=f"(r) : "f"(x)); return r;
}

// Exact-class GELU via A&S 7.1.28 (deg-6, ^-16): |erf err|<=3e-7, branch-free.
// Restored to deg-6 so the whole 1e-3 budget goes to the fp16 GEMM rounding.
__device__ __forceinline__ ull gelu2(ull s) {
    const ull C_ISQ2 = pkc(0.70710678118654752f);
    ull z = mul2(s & 0x7FFFFFFF7FFFFFFFULL, C_ISQ2);
    ull d = fma2(z, pkc(0.0000430638f), pkc(0.0002765672f));
    d = fma2(z, d, pkc(0.0001520143f));
    d = fma2(z, d, pkc(0.0092705272f));
    d = fma2(z, d, pkc(0.0422820123f));
    d = fma2(z, d, pkc(0.0705230784f));
    d = fma2(z, d, pkc(1.0f));
    d = mul2(d, d); d = mul2(d, d); d = mul2(d, d); d = mul2(d, d);   // d^16
    float dl, dh; unpk(d, dl, dh);
    ull r = pk2(frcp(dl), frcp(dh));                   // d^-16
    ull u = mul2(z, C_ISQ2);                           // 0.5|x|
    ull w = fma2(r ^ 0x8000000080000000ULL, u, u);     // u(1-r)
    return fma2(s, pkc(0.5f), w);                      // + 0.5x
}

// packed f32 pair -> f16x2 (lo half = first element)
__device__ __forceinline__ unsigned cvt16(ull v) {
    float f0, f1; unpk(v, f0, f1);
    unsigned h;
    asm("cvt.rn.f16x2.f32 %0, %1, %2;" : "=r"(h) : "f"(f1), "f"(f0));
    return h;
}

// D += A(m16k16 f16, row) @ B(k16n8 f16, col); fp32 accum. Baseline PTX (sm_80+).
__device__ __forceinline__ void mma16816(float d[4], const unsigned a[4],
                                         unsigned b0, unsigned b1) {
    asm("mma.sync.aligned.m16n8k16.row.col.f32.f16.f16.f32 "
        "{%0,%1,%2,%3},{%4,%5,%6,%7},{%8,%9},{%0,%1,%2,%3};"
        : "+f"(d[0]), "+f"(d[1]), "+f"(d[2]), "+f"(d[3])
        : "r"(a[0]), "r"(a[1]), "r"(a[2]), "r"(a[3]), "r"(b0), "r"(b1));
}

// ---- one-shot fold kernel: BN-fold + fp16 convert into fragment layouts ----
__global__ void fold_kernel(
    const float* __restrict__ W1, const float* __restrict__ g1, const float* __restrict__ b1,
    const float* __restrict__ m1, const float* __restrict__ v1,
    const float* __restrict__ W2, const float* __restrict__ g2, const float* __restrict__ b2,
    const float* __restrict__ m2, const float* __restrict__ v2,
    const float* __restrict__ W3, const float* __restrict__ g3, const float* __restrict__ b3,
    const float* __restrict__ m3, const float* __restrict__ v3)
{
    int i = blockIdx.x * blockDim.x + threadIdx.x;
    if (i < 2048) {                               // W1 [64x32], B-frag, 2 k-steps per 16B
        int o = i >> 5, k = i & 31;
        float w = W1[i] * (g1[o] * rsqrtf(v1[o] + EPS));
        int t = k >> 4, kk = k & 15, pp = (kk & 7) >> 1, half = kk >> 3, e = k & 1;
        int off = (o * 4 + pp) * 16 + t * 8 + half * 4 + e * 2;
        *(__half*)(wbuf + off) = __float2half(w);
    } else if (i < 2048 + 4096) {                 // W2 [64x64], B-frag, t-pair XOR swizzle
        int j = i - 2048, o = j >> 6, k = j & 63;
        float w = W2[j] * (g2[o] * rsqrtf(v2[o] + EPS));
        int t = k >> 4, kk = k & 15, pp = (kk & 7) >> 1, half = kk >> 3, e = k & 1;
        int tps = (t >> 1) ^ (o & 1), tlow = t & 1;
        int off = 4096 + ((o * 2 + tps) * 4 + pp) * 16 + tlow * 8 + half * 4 + e * 2;
        *(__half*)(wbuf + off) = __float2half(w);
    } else if (i < 2048 + 8192) {                 // W3 [64x64], A-frag layout
        int j = i - 6144, o = j >> 6, k = j & 63;
        float w = W3[j] * (g3[o] * rsqrtf(v3[o] + EPS));
        int mt = o >> 4, gg = o & 15, g = gg & 7, hi8 = gg >> 3;
        int t = k >> 4, kk = k & 15, pp = (kk & 7) >> 1, e = kk & 1, c8 = kk >> 3;
        int r = c8 * 2 + hi8;
        int off = 12288 + (mt * 4 + t) * 512 + ((g << 2) | pp) * 16 + r * 4 + e * 2;
        *(__half*)(wbuf + off) = __float2half(w);
    }
    if (i < 64) {
        bbuf[i]       = b1[i] - m1[i] * (g1[i] * rsqrtf(v1[i] + EPS));
        bbuf[64 + i]  = b2[i] - m2[i] * (g2[i] * rsqrtf(v2[i] + EPS));
        bbuf[128 + i] = b3[i] - m3[i] * (g3[i] * rsqrtf(v3[i] + EPS));
    }
    asm volatile("griddepcontrol.launch_dependents;");
}

// gelu + fp16 convert into next stage's A fragments
__device__ __forceinline__ void epilogue_mid(float D[8][4], unsigned Ah[4][4]) {
    #pragma unroll
    for (int j = 0; j < 8; ++j) {
        int t = j >> 1;
        int rb = (j & 1) ? 2 : 0;
        Ah[t][rb]     = cvt16(gelu2(pk2(D[j][0], D[j][1])));
        Ah[t][rb + 1] = cvt16(gelu2(pk2(D[j][2], D[j][3])));
    }
}

__global__ void __launch_bounds__(THREADS, 5) mlp_mma_kernel(
    const float* __restrict__ x, float* __restrict__ out)
{
    extern __shared__ char smem[];
    float* sbias = (float*)(smem + OFF_BIAS);
    char*  sw    = smem + OFF_W;

    const int tid = threadIdx.x;
    const int lane = tid & 31, wid = tid >> 5;   // warp = one 16-row m-tile
    const int g = lane >> 2, p = lane & 3;

    const int pbase = blockIdx.x * TILE_M;

    // ---- PDL phase 1 (fold-independent): fp16 A fragments straight from GMEM ----
    unsigned Ah[4][4];
    {
        const float* xr = x + (size_t)(pbase + wid * 16 + g) * 32;   // row g; row g+8 = +256
        #pragma unroll
        for (int t = 0; t < 2; ++t) {
            int c0 = p * 2 + t * 16;
            Ah[t][0] = cvt16(*(const ull*)(xr + c0));
            Ah[t][1] = cvt16(*(const ull*)(xr + 256 + c0));
            Ah[t][2] = cvt16(*(const ull*)(xr + c0 + 8));
            Ah[t][3] = cvt16(*(const ull*)(xr + 256 + c0 + 8));
        }
    }

    // ---- PDL phase 2: wait for weights, flat copy (1280 uint4 / 128 thr = 10x) ----
    asm volatile("griddepcontrol.wait;" ::: "memory");
    {
        const uint4* src = (const uint4*)wbuf;
        uint4* dst = (uint4*)sw;
        #pragma unroll
        for (int i = 0; i < 10; ++i) dst[tid + i * THREADS] = src[tid + i * THREADS];
        if (tid < 48) ((uint4*)sbias)[tid] = ((const uint4*)bbuf)[tid];
    }
    __syncthreads();

    float D[8][4];

    // ---- Stage 1: K=32 (2 k-steps), one LDS.128 per j ----
    #pragma unroll
    for (int j = 0; j < 8; ++j) {
        float b0, b1;
        unpk(*(const ull*)(sbias + 8 * j + 2 * p), b0, b1);
        D[j][0] = b0; D[j][1] = b1; D[j][2] = b0; D[j][3] = b1;
        int o = 8 * j + g;
        uint4 v = *(const uint4*)(sw + (o * 4 + p) * 16);
        mma16816(D[j], Ah[0], v.x, v.y);
        mma16816(D[j], Ah[1], v.z, v.w);
    }
    epilogue_mid(D, Ah);

    // ---- Stage 2: K=64 (4 k-steps), two LDS.128 per j (t-pair swizzled) ----
    #pragma unroll
    for (int j = 0; j < 8; ++j) {
        float b0, b1;
        unpk(*(const ull*)(sbias + 64 + 8 * j + 2 * p), b0, b1);
        D[j][0] = b0; D[j][1] = b1; D[j][2] = b0; D[j][3] = b1;
        int o = 8 * j + g;
        #pragma unroll
        for (int tp = 0; tp < 2; ++tp) {
            int ts = tp ^ (o & 1);
            uint4 v = *(const uint4*)(sw + 4096 + ((o * 2 + ts) * 4 + p) * 16);
            mma16816(D[j], Ah[2 * tp],     v.x, v.y);
            mma16816(D[j], Ah[2 * tp + 1], v.z, v.w);
        }
    }
    epilogue_mid(D, Ah);

    // ---- Stage 3: W3 as A (fp16 frag from SMEM), activations reused as B ----
    float D3[4][2][4];
    #pragma unroll
    for (int mt = 0; mt < 4; ++mt) {
        float blo = sbias[128 + 16 * mt + g];
        float bhi = sbias[128 + 16 * mt + g + 8];
        #pragma unroll
        for (int nb = 0; nb < 2; ++nb) {
            D3[mt][nb][0] = blo; D3[mt][nb][1] = blo;
            D3[mt][nb][2] = bhi; D3[mt][nb][3] = bhi;
        }
        #pragma unroll
        for (int t = 0; t < 4; ++t) {
            uint4 whv = *(const uint4*)(sw + 12288 + (mt * 4 + t) * 512 + lane * 16);
            unsigned wh[4] = {whv.x, whv.y, whv.z, whv.w};
            #pragma unroll
            for (int nb = 0; nb < 2; ++nb)
                mma16816(D3[mt][nb], wh, Ah[t][nb], Ah[t][nb + 2]);
        }
    }

    // ---- final: gelu -> STG.64 (adjacent points, same output channel) ----
    float* outp = out + (size_t)(pbase >> 10) * 65536 + (pbase & 1023) + wid * 16;
    #pragma unroll
    for (int mt = 0; mt < 4; ++mt) {
        #pragma unroll
        for (int nb = 0; nb < 2; ++nb) {
            ull v0 = gelu2(pk2(D3[mt][nb][0], D3[mt][nb][1]));
            ull v1 = gelu2(pk2(D3[mt][nb][2], D3[mt][nb][3]));
            float* a = outp + (size_t)(16 * mt + g) * 1024 + 8 * nb + 2 * p;
            *(ull*)a = v0;
            *(ull*)(a + 8 * 1024) = v1;
        }
    }
}

extern "C" void kernel_launch(void* const* d_in, const int* in_sizes, int n_in,
                              void* d_out, int out_size)
{
    const float* x  = (const float*)d_in[0];
    const float* W1 = (const float*)d_in[1];
    const float* g1 = (const float*)d_in[2];
    const float* b1 = (const float*)d_in[3];
    const float* m1 = (const float*)d_in[4];
    const float* v1 = (const float*)d_in[5];
    const float* W2 = (const float*)d_in[6];
    const float* g2 = (const float*)d_in[7];
    const float* b2 = (const float*)d_in[8];
    const float* m2 = (const float*)d_in[9];
    const float* v2 = (const float*)d_in[10];
    const float* W3 = (const float*)d_in[11];
    const float* g3 = (const float*)d_in[12];
    const float* b3 = (const float*)d_in[13];
    const float* m3 = (const float*)d_in[14];
    const float* v3 = (const float*)d_in[15];
    float* out = (float*)d_out;

    fold_kernel<<<40, 256>>>(W1, g1, b1, m1, v1, W2, g2, b2, m2, v2, W3, g3, b3, m3, v3);

    cudaFuncSetAttribute(mlp_mma_kernel,
                         cudaFuncAttributeMaxDynamicSharedMemorySize, SMEM_BYTES);

    cudaLaunchConfig_t cfg = {};
    cfg.gridDim = dim3(NBLK, 1, 1);
    cfg.blockDim = dim3(THREADS, 1, 1);
    cfg.dynamicSmemBytes = SMEM_BYTES;
    cfg.stream = 0;
    cudaLaunchAttribute attrs[1];
    attrs[0].id = cudaLaunchAttributeProgrammaticStreamSerialization;
    attrs[0].val.programmaticStreamSerializationAllowed = 1;
    cfg.attrs = attrs;
    cfg.numAttrs = 1;
    cudaLaunchKernelEx(&cfg, mlp_mma_kernel, x, out);
}

// round 17
// speedup vs baseline: 1.4896x; 1.1328x over previous
#include <cuda_runtime.h>
#include <cuda_fp16.h>

#define EPS      1e-5f
#define THREADS  128                 // 4 warps x m16 rows
#define TILE_M   64
#define NPTS     (64 * 1024)
#define NBLK     (NPTS / TILE_M)     // 1024 CTAs

// ---- pre-folded fp16 weights ----
// W1 @0 (4096B): B-frag layout, 16B unit(o,p) = [t0:b0,b1 | t1:b0,b1]
// W2 @4096 (8192B): 16B unit(o,tp,p) = [t=2tp:b0,b1 | t=2tp+1:b0,b1], tp XOR (o&1)
// W3 @12288 (8192B): A-frag layout, per (mt,t) 512B block: a[4] (16B) at lane*16
__device__ __align__(16) char  wbuf[20480];
__device__ __align__(16) float bbuf[192];

// ---- dynamic SMEM layout (bytes) ----
#define OFF_BIAS 0                   // 192 f32 (pad to 1024)
#define OFF_W    1024
#define SMEM_BYTES (OFF_W + 20480)   // 21504 -> 5 CTAs/SM

typedef unsigned long long ull;

// ---- packed fp32x2 helpers ----
__device__ __forceinline__ ull fma2(ull a, ull b, ull c) {
    ull d; asm("fma.rn.f32x2 %0,%1,%2,%3;" : "=l"(d) : "l"(a), "l"(b), "l"(c)); return d;
}
__device__ __forceinline__ ull mul2(ull a, ull b) {
    ull d; asm("mul.rn.f32x2 %0,%1,%2;" : "=l"(d) : "l"(a), "l"(b)); return d;
}
__device__ __forceinline__ void unpk(ull v, float& lo, float& hi) {
    asm("mov.b64 {%0,%1}, %2;" : "=f"(lo), "=f"(hi) : "l"(v));
}
__device__ __forceinline__ ull pk2(float lo, float hi) {
    ull v; asm("mov.b64 %0, {%1,%2};" : "=l"(v) : "f"(lo), "f"(hi)); return v;
}
__device__ __forceinline__ ull pkc(float c) {
    unsigned u = __float_as_uint(c); return ((ull)u << 32) | (ull)u;
}
__device__ __forceinline__ float frcp(float x) {
    float r; asm("rcp.approx.f32 %0,%1;" : "=f"(r) : "f"(x)); return r;
}

// GELU on a packed pair via A&S 7.1.27 (deg-4, ^-4): |erf err|<=5e-4 abs, 13 ops.
// Error stack (measured separately, independent sources): fp16 GEMM 3.75e-4 +
// deg-4 GELU 4.38e-4 -> RMS ~5.8e-4, worst-case 8.1e-4, vs 1e-3 budget.
__device__ __forceinline__ ull gelu2(ull s) {
    const ull C_ISQ2 = pkc(0.70710678118654752f);
    ull z = mul2(s & 0x7FFFFFFF7FFFFFFFULL, C_ISQ2);
    ull d = fma2(z, pkc(0.078108f), pkc(0.000972f));
    d = fma2(z, d, pkc(0.230389f));
    d = fma2(z, d, pkc(0.278393f));
    d = fma2(z, d, pkc(1.0f));
    d = mul2(d, d); d = mul2(d, d);                    // d^4
    float dl, dh; unpk(d, dl, dh);
    ull r = pk2(frcp(dl), frcp(dh));                   // d^-4
    ull u = mul2(z, C_ISQ2);                           // 0.5|x|
    ull w = fma2(r ^ 0x8000000080000000ULL, u, u);     // u(1-r)
    return fma2(s, pkc(0.5f), w);                      // + 0.5x
}

// packed f32 pair -> f16x2 (lo half = first element)
__device__ __forceinline__ unsigned cvt16(ull v) {
    float f0, f1; unpk(v, f0, f1);
    unsigned h;
    asm("cvt.rn.f16x2.f32 %0, %1, %2;" : "=r"(h) : "f"(f1), "f"(f0));
    return h;
}

// D += A(m16k16 f16, row) @ B(k16n8 f16, col); fp32 accum. Baseline PTX (sm_80+).
__device__ __forceinline__ void mma16816(float d[4], const unsigned a[4],
                                         unsigned b0, unsigned b1) {
    asm("mma.sync.aligned.m16n8k16.row.col.f32.f16.f16.f32 "
        "{%0,%1,%2,%3},{%4,%5,%6,%7},{%8,%9},{%0,%1,%2,%3};"
        : "+f"(d[0]), "+f"(d[1]), "+f"(d[2]), "+f"(d[3])
        : "r"(a[0]), "r"(a[1]), "r"(a[2]), "r"(a[3]), "r"(b0), "r"(b1));
}

// ---- one-shot fold kernel: BN-fold + fp16 convert into fragment layouts ----
__global__ void fold_kernel(
    const float* __restrict__ W1, const float* __restrict__ g1, const float* __restrict__ b1,
    const float* __restrict__ m1, const float* __restrict__ v1,
    const float* __restrict__ W2, const float* __restrict__ g2, const float* __restrict__ b2,
    const float* __restrict__ m2, const float* __restrict__ v2,
    const float* __restrict__ W3, const float* __restrict__ g3, const float* __restrict__ b3,
    const float* __restrict__ m3, const float* __restrict__ v3)
{
    int i = blockIdx.x * blockDim.x + threadIdx.x;
    if (i < 2048) {                               // W1 [64x32], B-frag, 2 k-steps per 16B
        int o = i >> 5, k = i & 31;
        float w = W1[i] * (g1[o] * rsqrtf(v1[o] + EPS));
        int t = k >> 4, kk = k & 15, pp = (kk & 7) >> 1, half = kk >> 3, e = k & 1;
        int off = (o * 4 + pp) * 16 + t * 8 + half * 4 + e * 2;
        *(__half*)(wbuf + off) = __float2half(w);
    } else if (i < 2048 + 4096) {                 // W2 [64x64], B-frag, t-pair XOR swizzle
        int j = i - 2048, o = j >> 6, k = j & 63;
        float w = W2[j] * (g2[o] * rsqrtf(v2[o] + EPS));
        int t = k >> 4, kk = k & 15, pp = (kk & 7) >> 1, half = kk >> 3, e = k & 1;
        int tps = (t >> 1) ^ (o & 1), tlow = t & 1;
        int off = 4096 + ((o * 2 + tps) * 4 + pp) * 16 + tlow * 8 + half * 4 + e * 2;
        *(__half*)(wbuf + off) = __float2half(w);
    } else if (i < 2048 + 8192) {                 // W3 [64x64], A-frag layout
        int j = i - 6144, o = j >> 6, k = j & 63;
        float w = W3[j] * (g3[o] * rsqrtf(v3[o] + EPS));
        int mt = o >> 4, gg = o & 15, g = gg & 7, hi8 = gg >> 3;
        int t = k >> 4, kk = k & 15, pp = (kk & 7) >> 1, e = kk & 1, c8 = kk >> 3;
        int r = c8 * 2 + hi8;
        int off = 12288 + (mt * 4 + t) * 512 + ((g << 2) | pp) * 16 + r * 4 + e * 2;
        *(__half*)(wbuf + off) = __float2half(w);
    }
    if (i < 64) {
        bbuf[i]       = b1[i] - m1[i] * (g1[i] * rsqrtf(v1[i] + EPS));
        bbuf[64 + i]  = b2[i] - m2[i] * (g2[i] * rsqrtf(v2[i] + EPS));
        bbuf[128 + i] = b3[i] - m3[i] * (g3[i] * rsqrtf(v3[i] + EPS));
    }
    asm volatile("griddepcontrol.launch_dependents;");
}

// gelu + fp16 convert into next stage's A fragments
__device__ __forceinline__ void epilogue_mid(float D[8][4], unsigned Ah[4][4]) {
    #pragma unroll
    for (int j = 0; j < 8; ++j) {
        int t = j >> 1;
        int rb = (j & 1) ? 2 : 0;
        Ah[t][rb]     = cvt16(gelu2(pk2(D[j][0], D[j][1])));
        Ah[t][rb + 1] = cvt16(gelu2(pk2(D[j][2], D[j][3])));
    }
}

__global__ void __launch_bounds__(THREADS, 5) mlp_mma_kernel(
    const float* __restrict__ x, float* __restrict__ out)
{
    extern __shared__ char smem[];
    float* sbias = (float*)(smem + OFF_BIAS);
    char*  sw    = smem + OFF_W;

    const int tid = threadIdx.x;
    const int lane = tid & 31, wid = tid >> 5;   // warp = one 16-row m-tile
    const int g = lane >> 2, p = lane & 3;

    const int pbase = blockIdx.x * TILE_M;

    // ---- PDL phase 1 (fold-independent): fp16 A fragments straight from GMEM ----
    unsigned Ah[4][4];
    {
        const float* xr = x + (size_t)(pbase + wid * 16 + g) * 32;   // row g; row g+8 = +256
        #pragma unroll
        for (int t = 0; t < 2; ++t) {
            int c0 = p * 2 + t * 16;
            Ah[t][0] = cvt16(*(const ull*)(xr + c0));
            Ah[t][1] = cvt16(*(const ull*)(xr + 256 + c0));
            Ah[t][2] = cvt16(*(const ull*)(xr + c0 + 8));
            Ah[t][3] = cvt16(*(const ull*)(xr + 256 + c0 + 8));
        }
    }

    // ---- PDL phase 2: wait for weights, flat copy (1280 uint4 / 128 thr = 10x) ----
    asm volatile("griddepcontrol.wait;" ::: "memory");
    {
        const uint4* src = (const uint4*)wbuf;
        uint4* dst = (uint4*)sw;
        #pragma unroll
        for (int i = 0; i < 10; ++i) dst[tid + i * THREADS] = src[tid + i * THREADS];
        if (tid < 48) ((uint4*)sbias)[tid] = ((const uint4*)bbuf)[tid];
    }
    __syncthreads();

    float D[8][4];

    // ---- Stage 1: K=32 (2 k-steps), one LDS.128 per j ----
    #pragma unroll
    for (int j = 0; j < 8; ++j) {
        float b0, b1;
        unpk(*(const ull*)(sbias + 8 * j + 2 * p), b0, b1);
        D[j][0] = b0; D[j][1] = b1; D[j][2] = b0; D[j][3] = b1;
        int o = 8 * j + g;
        uint4 v = *(const uint4*)(sw + (o * 4 + p) * 16);
        mma16816(D[j], Ah[0], v.x, v.y);
        mma16816(D[j], Ah[1], v.z, v.w);
    }
    epilogue_mid(D, Ah);

    // ---- Stage 2: K=64 (4 k-steps), two LDS.128 per j (t-pair swizzled) ----
    #pragma unroll
    for (int j = 0; j < 8; ++j) {
        float b0, b1;
        unpk(*(const ull*)(sbias + 64 + 8 * j + 2 * p), b0, b1);
        D[j][0] = b0; D[j][1] = b1; D[j][2] = b0; D[j][3] = b1;
        int o = 8 * j + g;
        #pragma unroll
        for (int tp = 0; tp < 2; ++tp) {
            int ts = tp ^ (o & 1);
            uint4 v = *(const uint4*)(sw + 4096 + ((o * 2 + ts) * 4 + p) * 16);
            mma16816(D[j], Ah[2 * tp],     v.x, v.y);
            mma16816(D[j], Ah[2 * tp + 1], v.z, v.w);
        }
    }
    epilogue_mid(D, Ah);

    // ---- Stage 3: W3 as A (fp16 frag from SMEM), activations reused as B ----
    float D3[4][2][4];
    #pragma unroll
    for (int mt = 0; mt < 4; ++mt) {
        float blo = sbias[128 + 16 * mt + g];
        float bhi = sbias[128 + 16 * mt + g + 8];
        #pragma unroll
        for (int nb = 0; nb < 2; ++nb) {
            D3[mt][nb][0] = blo; D3[mt][nb][1] = blo;
            D3[mt][nb][2] = bhi; D3[mt][nb][3] = bhi;
        }
        #pragma unroll
        for (int t = 0; t < 4; ++t) {
            uint4 whv = *(const uint4*)(sw + 12288 + (mt * 4 + t) * 512 + lane * 16);
            unsigned wh[4] = {whv.x, whv.y, whv.z, whv.w};
            #pragma unroll
            for (int nb = 0; nb < 2; ++nb)
                mma16816(D3[mt][nb], wh, Ah[t][nb], Ah[t][nb + 2]);
        }
    }

    // ---- final: gelu -> STG.64 (adjacent points, same output channel) ----
    float* outp = out + (size_t)(pbase >> 10) * 65536 + (pbase & 1023) + wid * 16;
    #pragma unroll
    for (int mt = 0; mt < 4; ++mt) {
        #pragma unroll
        for (int nb = 0; nb < 2; ++nb) {
            ull v0 = gelu2(pk2(D3[mt][nb][0], D3[mt][nb][1]));
            ull v1 = gelu2(pk2(D3[mt][nb][2], D3[mt][nb][3]));
            float* a = outp + (size_t)(16 * mt + g) * 1024 + 8 * nb + 2 * p;
            *(ull*)a = v0;
            *(ull*)(a + 8 * 1024) = v1;
        }
    }
}

extern "C" void kernel_launch(void* const* d_in, const int* in_sizes, int n_in,
                              void* d_out, int out_size)
{
    const float* x  = (const float*)d_in[0];
    const float* W1 = (const float*)d_in[1];
    const float* g1 = (const float*)d_in[2];
    const float* b1 = (const float*)d_in[3];
    const float* m1 = (const float*)d_in[4];
    const float* v1 = (const float*)d_in[5];
    const float* W2 = (const float*)d_in[6];
    const float* g2 = (const float*)d_in[7];
    const float* b2 = (const float*)d_in[8];
    const float* m2 = (const float*)d_in[9];
    const float* v2 = (const float*)d_in[10];
    const float* W3 = (const float*)d_in[11];
    const float* g3 = (const float*)d_in[12];
    const float* b3 = (const float*)d_in[13];
    const float* m3 = (const float*)d_in[14];
    const float* v3 = (const float*)d_in[15];
    float* out = (float*)d_out;

    fold_kernel<<<40, 256>>>(W1, g1, b1, m1, v1, W2, g2, b2, m2, v2, W3, g3, b3, m3, v3);

    cudaFuncSetAttribute(mlp_mma_kernel,
                         cudaFuncAttributeMaxDynamicSharedMemorySize, SMEM_BYTES);

    cudaLaunchConfig_t cfg = {};
    cfg.gridDim = dim3(NBLK, 1, 1);
    cfg.blockDim = dim3(THREADS, 1, 1);
    cfg.dynamicSmemBytes = SMEM_BYTES;
    cfg.stream = 0;
    cudaLaunchAttribute attrs[1];
    attrs[0].id = cudaLaunchAttributeProgrammaticStreamSerialization;
    attrs[0].val.programmaticStreamSerializationAllowed = 1;
    cfg.attrs = attrs;
    cfg.numAttrs = 1;
    cudaLaunchKernelEx(&cfg, mlp_mma_kernel, x, out);
}